// round 1
// baseline (speedup 1.0000x reference)
#include <cuda_runtime.h>
#include <cuda_bf16.h>
#include <math.h>

// Problem constants
#define S    2048
#define HID  4096
#define NH   64
#define HD   64
#define ROT  32
#define QKV3 12288   // 3*HID
#define EPS  1e-5f

// ---------------- scratch (device globals; no allocation allowed) ----------
__device__ float g_fused[S * QKV3];        // [S, 12288] qkv interleaved per head
__device__ float g_Q[NH * S * HD];         // [h][s][d]
__device__ float g_K[NH * S * HD];
__device__ float g_V[NH * S * HD];
__device__ float g_attn[S * HID];          // [s, h*64+d]  (ready for dense GEMM)

// ---------------- SGEMM: C[M,N] = A[M,K] @ B[K,N] + bias[N] ----------------
// 128x128 block tile, BK=8, 256 threads, 8x8 per thread (4+4 split vectors).
#define BM 128
#define BN 128
#define BK 8

__global__ __launch_bounds__(256, 2)
void sgemm_bias(const float* __restrict__ A, const float* __restrict__ B,
                const float* __restrict__ bias, float* __restrict__ C,
                int M, int N, int K)
{
    __shared__ float As[BK][BM];
    __shared__ float Bs[BK][BN];

    const int tid = threadIdx.x;
    const int tx = tid & 15;         // 0..15  (N direction)
    const int ty = tid >> 4;         // 0..15  (M direction)

    const int bx = blockIdx.x;       // N tile
    const int by = blockIdx.y;       // M tile

    // A tile load: 128 rows x 8 cols -> one float4 per thread
    const int arow = tid >> 1;            // 0..127
    const int acol = (tid & 1) * 4;       // 0 or 4
    // B tile load: 8 rows x 128 cols -> one float4 per thread
    const int brow = tid >> 5;            // 0..7
    const int bcol = (tid & 31) * 4;      // 0..124

    const float* Aptr = A + (size_t)(by * BM + arow) * K + acol;
    const float* Bptr = B + (size_t)brow * N + (size_t)bx * BN + bcol;

    float acc[8][8];
    #pragma unroll
    for (int i = 0; i < 8; i++)
        #pragma unroll
        for (int j = 0; j < 8; j++) acc[i][j] = 0.f;

    for (int k0 = 0; k0 < K; k0 += BK) {
        float4 av = *(const float4*)Aptr;
        As[acol + 0][arow] = av.x;
        As[acol + 1][arow] = av.y;
        As[acol + 2][arow] = av.z;
        As[acol + 3][arow] = av.w;
        *(float4*)&Bs[brow][bcol] = *(const float4*)Bptr;
        __syncthreads();

        #pragma unroll
        for (int k = 0; k < BK; k++) {
            float a[8], b[8];
            float4 a0 = *(const float4*)&As[k][ty * 4];
            float4 a1 = *(const float4*)&As[k][64 + ty * 4];
            float4 b0 = *(const float4*)&Bs[k][tx * 4];
            float4 b1 = *(const float4*)&Bs[k][64 + tx * 4];
            a[0]=a0.x; a[1]=a0.y; a[2]=a0.z; a[3]=a0.w;
            a[4]=a1.x; a[5]=a1.y; a[6]=a1.z; a[7]=a1.w;
            b[0]=b0.x; b[1]=b0.y; b[2]=b0.z; b[3]=b0.w;
            b[4]=b1.x; b[5]=b1.y; b[6]=b1.z; b[7]=b1.w;
            #pragma unroll
            for (int i = 0; i < 8; i++)
                #pragma unroll
                for (int j = 0; j < 8; j++)
                    acc[i][j] = fmaf(a[i], b[j], acc[i][j]);
        }
        __syncthreads();
        Aptr += BK;
        Bptr += (size_t)BK * N;
    }

    // epilogue: rows {by*128 + ih*64 + ty*4 + i}, cols {bx*128 + jh*64 + tx*4 + j}
    #pragma unroll
    for (int ih = 0; ih < 2; ih++) {
        #pragma unroll
        for (int i = 0; i < 4; i++) {
            int row = by * BM + ih * 64 + ty * 4 + i;
            #pragma unroll
            for (int jh = 0; jh < 2; jh++) {
                int col = bx * BN + jh * 64 + tx * 4;
                float4 v;
                v.x = acc[ih*4 + i][jh*4 + 0] + bias[col + 0];
                v.y = acc[ih*4 + i][jh*4 + 1] + bias[col + 1];
                v.z = acc[ih*4 + i][jh*4 + 2] + bias[col + 2];
                v.w = acc[ih*4 + i][jh*4 + 3] + bias[col + 3];
                *(float4*)&C[(size_t)row * N + col] = v;
            }
        }
    }
}

// ---------------- LayerNorm (per-head) + RoPE + scatter to [h][s][d] -------
// grid (S, NH), block 64 (one thread per d)
__global__ void ln_rope_kernel(const float* __restrict__ fused,
                               const float* __restrict__ qw, const float* __restrict__ qb,
                               const float* __restrict__ kw, const float* __restrict__ kb,
                               float* __restrict__ Q, float* __restrict__ K,
                               float* __restrict__ V)
{
    const int s = blockIdx.x;
    const int h = blockIdx.y;
    const int d = threadIdx.x;
    const int w = d >> 5;
    const int lane = d & 31;

    const float* base = fused + (size_t)s * QKV3 + h * (3 * HD);
    float q = base[d];
    float k = base[HD + d];
    float v = base[2 * HD + d];

    __shared__ float sh[2];

    // --- helper: sum over 64 threads ---
    auto bsum = [&](float x) -> float {
        #pragma unroll
        for (int o = 16; o; o >>= 1) x += __shfl_xor_sync(0xffffffffu, x, o);
        __syncthreads();
        if (lane == 0) sh[w] = x;
        __syncthreads();
        return sh[0] + sh[1];
    };

    // LN for q
    float mu = bsum(q) * (1.f / HD);
    float dq = q - mu;
    float var = bsum(dq * dq) * (1.f / HD);
    float qn = dq * rsqrtf(var + EPS) * qw[d] + qb[d];

    // LN for k
    mu = bsum(k) * (1.f / HD);
    float dk = k - mu;
    var = bsum(dk * dk) * (1.f / HD);
    float kn = dk * rsqrtf(var + EPS) * kw[d] + kb[d];

    // RoPE on first ROT=32 dims (warp 0 only participates meaningfully)
    float qo = __shfl_xor_sync(0xffffffffu, qn, 16);
    float ko = __shfl_xor_sync(0xffffffffu, kn, 16);
    if (d < ROT) {
        int f = d & 15;
        float invf = (float)pow(25000.0, -(double)f / 16.0);
        float ph = (float)s * invf;
        float c = cosf(ph);
        float si = sinf(ph);
        float sign = (d < 16) ? -1.f : 1.f;
        qn = qn * c + sign * qo * si;
        kn = kn * c + sign * ko * si;
    }

    size_t o = ((size_t)h * S + s) * HD + d;
    Q[o] = qn;
    K[o] = kn;
    V[o] = v;
}

// ---------------- causal attention, streaming softmax ----------------------
// grid (S/8, NH); block 256 = 8 warps; warp w handles query q0+w of head h.
// Output written as [s, h*64 + d]  -> directly consumable by dense GEMM.
__global__ __launch_bounds__(256, 4)
void attn_kernel(const float* __restrict__ Q, const float* __restrict__ K,
                 const float* __restrict__ V, float* __restrict__ O)
{
    const int h = blockIdx.y;
    const int q0 = blockIdx.x * 8;
    const int warp = threadIdx.x >> 5;
    const int lane = threadIdx.x & 31;
    const int qi = q0 + warp;

    __shared__ float Ks[64 * 64];
    __shared__ float Vs[64 * 64];

    float2 qv = *(const float2*)(Q + ((size_t)h * S + qi) * HD + lane * 2);

    float2 acc = make_float2(0.f, 0.f);
    float m = -INFINITY, l = 0.f;

    const int nk = qi + 1;                         // causal key count for this warp
    const int ntiles = (q0 + 7) / 64 + 1;          // tiles needed by the block

    for (int t = 0; t < ntiles; t++) {
        const int k0 = t * 64;
        const float4* kp = (const float4*)(K + ((size_t)h * S + k0) * HD);
        const float4* vp = (const float4*)(V + ((size_t)h * S + k0) * HD);
        for (int i = threadIdx.x; i < 64 * 64 / 4; i += 256) {
            ((float4*)Ks)[i] = kp[i];
            ((float4*)Vs)[i] = vp[i];
        }
        __syncthreads();

        const int jmax = min(64, nk - k0);
        for (int j = 0; j < jmax; j++) {
            float2 kv = *(const float2*)&Ks[j * 64 + lane * 2];
            float p = qv.x * kv.x + qv.y * kv.y;
            p += __shfl_xor_sync(0xffffffffu, p, 16);
            p += __shfl_xor_sync(0xffffffffu, p, 8);
            p += __shfl_xor_sync(0xffffffffu, p, 4);
            p += __shfl_xor_sync(0xffffffffu, p, 2);
            p += __shfl_xor_sync(0xffffffffu, p, 1);
            float logit = p * 0.125f;               // 1/sqrt(64)
            float mn = fmaxf(m, logit);
            float corr = __expf(m - mn);
            float wgt = __expf(logit - mn);
            l = l * corr + wgt;
            float2 vv = *(const float2*)&Vs[j * 64 + lane * 2];
            acc.x = acc.x * corr + wgt * vv.x;
            acc.y = acc.y * corr + wgt * vv.y;
            m = mn;
        }
        __syncthreads();
    }

    float inv = 1.f / l;
    float2 ov = make_float2(acc.x * inv, acc.y * inv);
    *(float2*)(O + (size_t)qi * HID + h * HD + lane * 2) = ov;
}

// ---------------- launch ---------------------------------------------------
extern "C" void kernel_launch(void* const* d_in, const int* in_sizes, int n_in,
                              void* d_out, int out_size)
{
    const float* hs    = (const float*)d_in[0];
    // d_in[1] = attention_mask (pure causal, implicit), d_in[2] = position_ids (arange)
    const float* Wqkv  = (const float*)d_in[3];
    const float* bqkv  = (const float*)d_in[4];
    const float* Wd    = (const float*)d_in[5];
    const float* bd    = (const float*)d_in[6];
    const float* qw    = (const float*)d_in[7];
    const float* qb    = (const float*)d_in[8];
    const float* kw    = (const float*)d_in[9];
    const float* kb    = (const float*)d_in[10];
    float* out = (float*)d_out;

    float *fused, *Q, *K, *V, *attn;
    cudaGetSymbolAddress((void**)&fused, g_fused);
    cudaGetSymbolAddress((void**)&Q,     g_Q);
    cudaGetSymbolAddress((void**)&K,     g_K);
    cudaGetSymbolAddress((void**)&V,     g_V);
    cudaGetSymbolAddress((void**)&attn,  g_attn);

    // 1) fused QKV GEMM: [2048,4096] @ [4096,12288] + b
    sgemm_bias<<<dim3(QKV3 / BN, S / BM), 256>>>(hs, Wqkv, bqkv, fused, S, QKV3, HID);

    // 2) per-head LN + RoPE, scatter to [h][s][d]
    ln_rope_kernel<<<dim3(S, NH), HD>>>(fused, qw, qb, kw, kb, Q, K, V);

    // 3) causal attention -> [s, h*64+d]
    attn_kernel<<<dim3(S / 8, NH), 256>>>(Q, K, V, attn);

    // 4) dense GEMM: [2048,4096] @ [4096,4096] + b -> out
    sgemm_bias<<<dim3(HID / BN, S / BM), 256>>>(attn, Wd, bd, out, S, HID, HID);
}

// round 3
// speedup vs baseline: 1.4863x; 1.4863x over previous
#include <cuda_runtime.h>
#include <cuda_bf16.h>
#include <math.h>
#include <stdint.h>

// Problem constants
#define S    2048
#define HID  4096
#define NH   64
#define HD   64
#define ROT  32
#define QKV3 12288   // 3*HID
#define EPS  1e-5f
#define KDIM 4096
#define BKB  32                  // k-chunk in bf16 elements (64 bytes)
#define KITERS (KDIM / BKB)      // 128

// ---------------- scratch (device globals; no allocation allowed) ----------
__device__ float g_fused[S * QKV3];
__device__ float g_Q[NH * S * HD];
__device__ float g_K[NH * S * HD];
__device__ float g_V[NH * S * HD];
__device__ float g_attn[S * HID];
__device__ __nv_bfloat16 g_Ah[S * HID];
__device__ __nv_bfloat16 g_Al[S * HID];
__device__ __nv_bfloat16 g_Bqh[QKV3 * HID];
__device__ __nv_bfloat16 g_Bql[QKV3 * HID];
__device__ __nv_bfloat16 g_Bdh[HID * HID];
__device__ __nv_bfloat16 g_Bdl[HID * HID];

// ===================== PTX helpers (sm_80-compatible only) =====================
__device__ __forceinline__ uint32_t smem_u32(const void* p) {
    uint32_t a;
    asm("{ .reg .u64 t; cvta.to.shared.u64 t, %1; cvt.u32.u64 %0, t; }" : "=r"(a) : "l"(p));
    return a;
}
__device__ __forceinline__ void cp16(uint32_t dst, const void* src) {
    asm volatile("cp.async.cg.shared.global [%0], [%1], 16;\n" :: "r"(dst), "l"(src));
}
__device__ __forceinline__ void cp_commit() { asm volatile("cp.async.commit_group;\n" ::: "memory"); }
__device__ __forceinline__ void cp_wait1()  { asm volatile("cp.async.wait_group 1;\n" ::: "memory"); }

__device__ __forceinline__ void ldsm4(uint32_t* r, uint32_t addr) {
    asm volatile("ldmatrix.sync.aligned.m8n8.x4.shared.b16 {%0,%1,%2,%3}, [%4];"
                 : "=r"(r[0]), "=r"(r[1]), "=r"(r[2]), "=r"(r[3]) : "r"(addr));
}
__device__ __forceinline__ void mma16816(float* d, const uint32_t* a, const uint32_t* b) {
    asm volatile("mma.sync.aligned.m16n8k16.row.col.f32.bf16.bf16.f32 "
                 "{%0,%1,%2,%3}, {%4,%5,%6,%7}, {%8,%9}, {%0,%1,%2,%3};"
                 : "+f"(d[0]), "+f"(d[1]), "+f"(d[2]), "+f"(d[3])
                 : "r"(a[0]), "r"(a[1]), "r"(a[2]), "r"(a[3]), "r"(b[0]), "r"(b[1]));
}

// swizzled byte offset inside a [128 rows x 64B] tile: 16B chunk kc of row
__device__ __forceinline__ uint32_t swz(int row, int kc) {
    return (uint32_t)(row * 64 + ((kc ^ ((row >> 1) & 3)) << 4));
}

// ===================== split / transpose conversion kernels =====================
__global__ void split_rows(const float* __restrict__ in, __nv_bfloat16* __restrict__ hi,
                           __nv_bfloat16* __restrict__ lo, int n4)
{
    int i = blockIdx.x * blockDim.x + threadIdx.x;
    if (i >= n4) return;
    float4 v = ((const float4*)in)[i];
    __nv_bfloat16 h0 = __float2bfloat16(v.x);
    __nv_bfloat16 h1 = __float2bfloat16(v.y);
    __nv_bfloat16 h2 = __float2bfloat16(v.z);
    __nv_bfloat16 h3 = __float2bfloat16(v.w);
    __nv_bfloat16 l0 = __float2bfloat16(v.x - __bfloat162float(h0));
    __nv_bfloat16 l1 = __float2bfloat16(v.y - __bfloat162float(h1));
    __nv_bfloat16 l2 = __float2bfloat16(v.z - __bfloat162float(h2));
    __nv_bfloat16 l3 = __float2bfloat16(v.w - __bfloat162float(h3));
    ((__nv_bfloat162*)hi)[2 * i]     = __nv_bfloat162(h0, h1);
    ((__nv_bfloat162*)hi)[2 * i + 1] = __nv_bfloat162(h2, h3);
    ((__nv_bfloat162*)lo)[2 * i]     = __nv_bfloat162(l0, l1);
    ((__nv_bfloat162*)lo)[2 * i + 1] = __nv_bfloat162(l2, l3);
}

// in [K, N] fp32 row-major -> out [N, K] bf16 hi/lo
__global__ void split_transpose(const float* __restrict__ in, __nv_bfloat16* __restrict__ hi,
                                __nv_bfloat16* __restrict__ lo, int K, int N)
{
    __shared__ float t[32][33];
    const int n0 = blockIdx.x * 32, k0 = blockIdx.y * 32;
    const int tx = threadIdx.x, ty = threadIdx.y;
    #pragma unroll
    for (int r = 0; r < 4; r++)
        t[ty + r * 8][tx] = in[(size_t)(k0 + ty + r * 8) * N + n0 + tx];
    __syncthreads();
    #pragma unroll
    for (int r = 0; r < 4; r++) {
        int n = n0 + ty + r * 8;
        int k = k0 + tx;
        float v = t[tx][ty + r * 8];
        __nv_bfloat16 h = __float2bfloat16(v);
        __nv_bfloat16 l = __float2bfloat16(v - __bfloat162float(h));
        hi[(size_t)n * K + k] = h;
        lo[(size_t)n * K + k] = l;
    }
}

// ===================== bf16x3 tensor-core GEMM (mma.sync) =====================
// C[M,N] = A[M,K] @ B[N,K]^T + bias. K=4096.
// grid(M/128, N/128), 256 threads = 8 warps (4 M x 2 N), warp tile 32x64.
// 3-stage cp.async pipeline; per stage: Ah(8K) Al(8K) Bh(8K) Bl(8K) = 32KB.
#define STG 32768
#define GEMM_SMEM (3 * STG)

__global__ __launch_bounds__(256)
void gemm_bf16x3(const __nv_bfloat16* __restrict__ Ah, const __nv_bfloat16* __restrict__ Al,
                 const __nv_bfloat16* __restrict__ Bh, const __nv_bfloat16* __restrict__ Bl,
                 const float* __restrict__ bias, float* __restrict__ C, int N)
{
    extern __shared__ __align__(128) char smem[];
    const uint32_t sb = smem_u32(smem);
    const int tid = threadIdx.x, warp = tid >> 5, lane = tid & 31;
    const int wm = warp >> 1, wn = warp & 1;           // 4 x 2 warp grid
    const int m0 = blockIdx.x * 128, n0 = blockIdx.y * 128;

    const char* srcs[4] = {
        (const char*)(Ah + (size_t)m0 * KDIM),
        (const char*)(Al + (size_t)m0 * KDIM),
        (const char*)(Bh + (size_t)n0 * KDIM),
        (const char*)(Bl + (size_t)n0 * KDIM)
    };

    // cp.async indices: per matrix 512 chunks of 16B; 2 per thread
    const int ldrow0 = tid >> 2, ldc = tid & 3;
    const uint32_t dsw0 = swz(ldrow0, ldc);
    const uint32_t dsw1 = swz(ldrow0 + 64, ldc);

    auto load_stage = [&](int st, int kc) {
        uint32_t base = sb + st * STG;
        size_t kb = (size_t)kc * 64;   // byte offset into each 8192B row
        #pragma unroll
        for (int mat = 0; mat < 4; mat++) {
            const char* s = srcs[mat];
            uint32_t d = base + mat * 8192;
            cp16(d + dsw0, s + (size_t)ldrow0 * 8192 + kb + ldc * 16);
            cp16(d + dsw1, s + (size_t)(ldrow0 + 64) * 8192 + kb + ldc * 16);
        }
    };

    // precompute ldmatrix lane offsets
    const int g = lane >> 3, r = lane & 7;
    uint32_t offA[2][2], offB[4][2];
    #pragma unroll
    for (int mt = 0; mt < 2; mt++)
        #pragma unroll
        for (int ks = 0; ks < 2; ks++) {
            int row = wm * 32 + mt * 16 + (g & 1) * 8 + r;
            int kc = ks * 2 + (g >> 1);
            offA[mt][ks] = swz(row, kc);
        }
    #pragma unroll
    for (int p = 0; p < 4; p++)
        #pragma unroll
        for (int ks = 0; ks < 2; ks++) {
            int row = wn * 64 + p * 16 + (g >> 1) * 8 + r;
            int kc = ks * 2 + (g & 1);
            offB[p][ks] = swz(row, kc);
        }

    float acc[2][8][4];
    #pragma unroll
    for (int mt = 0; mt < 2; mt++)
        #pragma unroll
        for (int nt = 0; nt < 8; nt++)
            #pragma unroll
            for (int q = 0; q < 4; q++) acc[mt][nt][q] = 0.f;

    load_stage(0, 0); cp_commit();
    load_stage(1, 1); cp_commit();

    int st = 0;
    for (int i = 0; i < KITERS; i++) {
        cp_wait1();
        __syncthreads();
        if (i + 2 < KITERS) load_stage((st + 2) % 3, i + 2);
        cp_commit();

        uint32_t base = sb + st * STG;
        #pragma unroll
        for (int ks = 0; ks < 2; ks++) {
            uint32_t ah[2][4], al[2][4], bh[8][2], bl[8][2];
            #pragma unroll
            for (int mt = 0; mt < 2; mt++) {
                ldsm4(ah[mt], base + offA[mt][ks]);
                ldsm4(al[mt], base + 8192 + offA[mt][ks]);
            }
            #pragma unroll
            for (int p = 0; p < 4; p++) {
                uint32_t t4[4];
                ldsm4(t4, base + 16384 + offB[p][ks]);
                bh[2*p][0] = t4[0]; bh[2*p][1] = t4[1];
                bh[2*p+1][0] = t4[2]; bh[2*p+1][1] = t4[3];
                ldsm4(t4, base + 24576 + offB[p][ks]);
                bl[2*p][0] = t4[0]; bl[2*p][1] = t4[1];
                bl[2*p+1][0] = t4[2]; bl[2*p+1][1] = t4[3];
            }
            #pragma unroll
            for (int mt = 0; mt < 2; mt++)
                #pragma unroll
                for (int nt = 0; nt < 8; nt++) {
                    mma16816(acc[mt][nt], ah[mt], bh[nt]);
                    mma16816(acc[mt][nt], ah[mt], bl[nt]);
                    mma16816(acc[mt][nt], al[mt], bh[nt]);
                }
        }
        st = (st + 1) % 3;
    }

    // epilogue: direct global stores + bias
    #pragma unroll
    for (int mt = 0; mt < 2; mt++) {
        int row0 = m0 + wm * 32 + mt * 16 + (lane >> 2);
        #pragma unroll
        for (int nt = 0; nt < 8; nt++) {
            int col = n0 + wn * 64 + nt * 8 + (lane & 3) * 2;
            float bx = __ldg(bias + col), by = __ldg(bias + col + 1);
            float2 v0 = make_float2(acc[mt][nt][0] + bx, acc[mt][nt][1] + by);
            float2 v1 = make_float2(acc[mt][nt][2] + bx, acc[mt][nt][3] + by);
            *(float2*)&C[(size_t)row0 * N + col] = v0;
            *(float2*)&C[(size_t)(row0 + 8) * N + col] = v1;
        }
    }
}

// ---------------- LayerNorm (per-head) + RoPE + scatter to [h][s][d] -------
__global__ void ln_rope_kernel(const float* __restrict__ fused,
                               const float* __restrict__ qw, const float* __restrict__ qb,
                               const float* __restrict__ kw, const float* __restrict__ kb,
                               float* __restrict__ Q, float* __restrict__ K,
                               float* __restrict__ V)
{
    const int s = blockIdx.x;
    const int h = blockIdx.y;
    const int d = threadIdx.x;
    const int w = d >> 5;
    const int lane = d & 31;

    const float* base = fused + (size_t)s * QKV3 + h * (3 * HD);
    float q = base[d];
    float k = base[HD + d];
    float v = base[2 * HD + d];

    __shared__ float sh[2];

    auto bsum = [&](float x) -> float {
        #pragma unroll
        for (int o = 16; o; o >>= 1) x += __shfl_xor_sync(0xffffffffu, x, o);
        __syncthreads();
        if (lane == 0) sh[w] = x;
        __syncthreads();
        return sh[0] + sh[1];
    };

    float mu = bsum(q) * (1.f / HD);
    float dq = q - mu;
    float var = bsum(dq * dq) * (1.f / HD);
    float qn = dq * rsqrtf(var + EPS) * qw[d] + qb[d];

    mu = bsum(k) * (1.f / HD);
    float dk = k - mu;
    var = bsum(dk * dk) * (1.f / HD);
    float kn = dk * rsqrtf(var + EPS) * kw[d] + kb[d];

    float qo = __shfl_xor_sync(0xffffffffu, qn, 16);
    float ko = __shfl_xor_sync(0xffffffffu, kn, 16);
    if (d < ROT) {
        int f = d & 15;
        float invf = (float)pow(25000.0, -(double)f / 16.0);
        float ph = (float)s * invf;
        float c = cosf(ph);
        float si = sinf(ph);
        float sign = (d < 16) ? -1.f : 1.f;
        qn = qn * c + sign * qo * si;
        kn = kn * c + sign * ko * si;
    }

    size_t o = ((size_t)h * S + s) * HD + d;
    Q[o] = qn;
    K[o] = kn;
    V[o] = v;
}

// ---------------- causal attention, streaming softmax ----------------------
__global__ __launch_bounds__(256, 4)
void attn_kernel(const float* __restrict__ Q, const float* __restrict__ K,
                 const float* __restrict__ V, float* __restrict__ O)
{
    const int h = blockIdx.y;
    const int q0 = blockIdx.x * 8;
    const int warp = threadIdx.x >> 5;
    const int lane = threadIdx.x & 31;
    const int qi = q0 + warp;

    __shared__ float Ks[64 * 64];
    __shared__ float Vs[64 * 64];

    float2 qv = *(const float2*)(Q + ((size_t)h * S + qi) * HD + lane * 2);

    float2 acc = make_float2(0.f, 0.f);
    float m = -INFINITY, l = 0.f;

    const int nk = qi + 1;
    const int ntiles = (q0 + 7) / 64 + 1;

    for (int t = 0; t < ntiles; t++) {
        const int k0 = t * 64;
        const float4* kp = (const float4*)(K + ((size_t)h * S + k0) * HD);
        const float4* vp = (const float4*)(V + ((size_t)h * S + k0) * HD);
        for (int i = threadIdx.x; i < 64 * 64 / 4; i += 256) {
            ((float4*)Ks)[i] = kp[i];
            ((float4*)Vs)[i] = vp[i];
        }
        __syncthreads();

        const int jmax = min(64, nk - k0);
        for (int j = 0; j < jmax; j++) {
            float2 kv = *(const float2*)&Ks[j * 64 + lane * 2];
            float p = qv.x * kv.x + qv.y * kv.y;
            p += __shfl_xor_sync(0xffffffffu, p, 16);
            p += __shfl_xor_sync(0xffffffffu, p, 8);
            p += __shfl_xor_sync(0xffffffffu, p, 4);
            p += __shfl_xor_sync(0xffffffffu, p, 2);
            p += __shfl_xor_sync(0xffffffffu, p, 1);
            float logit = p * 0.125f;
            float mn = fmaxf(m, logit);
            float corr = __expf(m - mn);
            float wgt = __expf(logit - mn);
            l = l * corr + wgt;
            float2 vv = *(const float2*)&Vs[j * 64 + lane * 2];
            acc.x = acc.x * corr + wgt * vv.x;
            acc.y = acc.y * corr + wgt * vv.y;
            m = mn;
        }
        __syncthreads();
    }

    float inv = 1.f / l;
    float2 ov = make_float2(acc.x * inv, acc.y * inv);
    *(float2*)(O + (size_t)qi * HID + h * HD + lane * 2) = ov;
}

// ---------------- launch ---------------------------------------------------
extern "C" void kernel_launch(void* const* d_in, const int* in_sizes, int n_in,
                              void* d_out, int out_size)
{
    const float* hs    = (const float*)d_in[0];
    const float* Wqkv  = (const float*)d_in[3];
    const float* bqkv  = (const float*)d_in[4];
    const float* Wd    = (const float*)d_in[5];
    const float* bd    = (const float*)d_in[6];
    const float* qw    = (const float*)d_in[7];
    const float* qb    = (const float*)d_in[8];
    const float* kw    = (const float*)d_in[9];
    const float* kb    = (const float*)d_in[10];
    float* out = (float*)d_out;

    float *fused, *Q, *K, *V, *attn;
    __nv_bfloat16 *Ahp, *Alp, *Bqh, *Bql, *Bdh, *Bdl;
    cudaGetSymbolAddress((void**)&fused, g_fused);
    cudaGetSymbolAddress((void**)&Q,     g_Q);
    cudaGetSymbolAddress((void**)&K,     g_K);
    cudaGetSymbolAddress((void**)&V,     g_V);
    cudaGetSymbolAddress((void**)&attn,  g_attn);
    cudaGetSymbolAddress((void**)&Ahp,   g_Ah);
    cudaGetSymbolAddress((void**)&Alp,   g_Al);
    cudaGetSymbolAddress((void**)&Bqh,   g_Bqh);
    cudaGetSymbolAddress((void**)&Bql,   g_Bql);
    cudaGetSymbolAddress((void**)&Bdh,   g_Bdh);
    cudaGetSymbolAddress((void**)&Bdl,   g_Bdl);

    static int smem_set = 0;
    if (!smem_set) {
        cudaFuncSetAttribute(gemm_bf16x3, cudaFuncAttributeMaxDynamicSharedMemorySize, GEMM_SMEM);
        smem_set = 1;
    }

    // 0) split/transpose weights + split activations
    split_rows<<<(S * HID / 4 + 255) / 256, 256>>>(hs, Ahp, Alp, S * HID / 4);
    split_transpose<<<dim3(QKV3 / 32, HID / 32), dim3(32, 8)>>>(Wqkv, Bqh, Bql, KDIM, QKV3);
    split_transpose<<<dim3(HID / 32, HID / 32), dim3(32, 8)>>>(Wd, Bdh, Bdl, KDIM, HID);

    // 1) QKV GEMM (tensor cores, bf16x3)
    gemm_bf16x3<<<dim3(S / 128, QKV3 / 128), 256, GEMM_SMEM>>>(Ahp, Alp, Bqh, Bql, bqkv, fused, QKV3);

    // 2) per-head LN + RoPE
    ln_rope_kernel<<<dim3(S, NH), HD>>>(fused, qw, qb, kw, kb, Q, K, V);

    // 3) causal attention
    attn_kernel<<<dim3(S / 8, NH), 256>>>(Q, K, V, attn);

    // 4) split attn output, dense GEMM -> out
    split_rows<<<(S * HID / 4 + 255) / 256, 256>>>(attn, Ahp, Alp, S * HID / 4);
    gemm_bf16x3<<<dim3(S / 128, HID / 128), 256, GEMM_SMEM>>>(Ahp, Alp, Bdh, Bdl, bd, out, HID);
}

// round 4
// speedup vs baseline: 3.5795x; 2.4083x over previous
#include <cuda_runtime.h>
#include <cuda_bf16.h>
#include <math.h>
#include <stdint.h>

// Problem constants
#define S    2048
#define HID  4096
#define NH   64
#define HD   64
#define ROT  32
#define QKV3 12288   // 3*HID
#define EPS  1e-5f
#define KDIM 4096
#define BKB  32
#define KITERS (KDIM / BKB)      // 128

// ---------------- scratch (device globals) ----------------
__device__ float g_fused[S * QKV3];
__device__ __nv_bfloat16 g_Ah[S * HID];
__device__ __nv_bfloat16 g_Al[S * HID];
__device__ __nv_bfloat16 g_Bqh[QKV3 * HID];
__device__ __nv_bfloat16 g_Bql[QKV3 * HID];
__device__ __nv_bfloat16 g_Bdh[HID * HID];
__device__ __nv_bfloat16 g_Bdl[HID * HID];
// attention operands, [h][s][d] bf16 hi/lo
__device__ __nv_bfloat16 g_Qh[NH * S * HD];
__device__ __nv_bfloat16 g_Ql[NH * S * HD];
__device__ __nv_bfloat16 g_Kh[NH * S * HD];
__device__ __nv_bfloat16 g_Kl[NH * S * HD];
__device__ __nv_bfloat16 g_Vh[NH * S * HD];
__device__ __nv_bfloat16 g_Vl[NH * S * HD];

// ===================== PTX helpers =====================
__device__ __forceinline__ uint32_t smem_u32(const void* p) {
    uint32_t a;
    asm("{ .reg .u64 t; cvta.to.shared.u64 t, %1; cvt.u32.u64 %0, t; }" : "=r"(a) : "l"(p));
    return a;
}
__device__ __forceinline__ void cp16(uint32_t dst, const void* src) {
    asm volatile("cp.async.cg.shared.global [%0], [%1], 16;\n" :: "r"(dst), "l"(src));
}
__device__ __forceinline__ void cp_commit() { asm volatile("cp.async.commit_group;\n" ::: "memory"); }
__device__ __forceinline__ void cp_wait1()  { asm volatile("cp.async.wait_group 1;\n" ::: "memory"); }

__device__ __forceinline__ void ldsm4(uint32_t* r, uint32_t addr) {
    asm volatile("ldmatrix.sync.aligned.m8n8.x4.shared.b16 {%0,%1,%2,%3}, [%4];"
                 : "=r"(r[0]), "=r"(r[1]), "=r"(r[2]), "=r"(r[3]) : "r"(addr));
}
__device__ __forceinline__ void ldsm4t(uint32_t* r, uint32_t addr) {
    asm volatile("ldmatrix.sync.aligned.m8n8.x4.trans.shared.b16 {%0,%1,%2,%3}, [%4];"
                 : "=r"(r[0]), "=r"(r[1]), "=r"(r[2]), "=r"(r[3]) : "r"(addr));
}
__device__ __forceinline__ void mma16816(float* d, const uint32_t* a, const uint32_t* b) {
    asm volatile("mma.sync.aligned.m16n8k16.row.col.f32.bf16.bf16.f32 "
                 "{%0,%1,%2,%3}, {%4,%5,%6,%7}, {%8,%9}, {%0,%1,%2,%3};"
                 : "+f"(d[0]), "+f"(d[1]), "+f"(d[2]), "+f"(d[3])
                 : "r"(a[0]), "r"(a[1]), "r"(a[2]), "r"(a[3]), "r"(b[0]), "r"(b[1]));
}

// 64-byte-row swizzle (GEMM tiles: 32 bf16/row)
__device__ __forceinline__ uint32_t swz64(int row, int kc) {
    return (uint32_t)(row * 64 + ((kc ^ ((row >> 1) & 3)) << 4));
}
// 128-byte-row swizzle (attention tiles: 64 bf16/row)
__device__ __forceinline__ uint32_t swz128(int row, int c) {
    return (uint32_t)(row * 128 + ((c ^ (row & 7)) << 4));
}

// ===================== split / transpose conversion kernels =====================
__global__ void split_rows(const float* __restrict__ in, __nv_bfloat16* __restrict__ hi,
                           __nv_bfloat16* __restrict__ lo, int n4)
{
    int i = blockIdx.x * blockDim.x + threadIdx.x;
    if (i >= n4) return;
    float4 v = ((const float4*)in)[i];
    __nv_bfloat16 h0 = __float2bfloat16(v.x);
    __nv_bfloat16 h1 = __float2bfloat16(v.y);
    __nv_bfloat16 h2 = __float2bfloat16(v.z);
    __nv_bfloat16 h3 = __float2bfloat16(v.w);
    __nv_bfloat16 l0 = __float2bfloat16(v.x - __bfloat162float(h0));
    __nv_bfloat16 l1 = __float2bfloat16(v.y - __bfloat162float(h1));
    __nv_bfloat16 l2 = __float2bfloat16(v.z - __bfloat162float(h2));
    __nv_bfloat16 l3 = __float2bfloat16(v.w - __bfloat162float(h3));
    ((__nv_bfloat162*)hi)[2 * i]     = __nv_bfloat162(h0, h1);
    ((__nv_bfloat162*)hi)[2 * i + 1] = __nv_bfloat162(h2, h3);
    ((__nv_bfloat162*)lo)[2 * i]     = __nv_bfloat162(l0, l1);
    ((__nv_bfloat162*)lo)[2 * i + 1] = __nv_bfloat162(l2, l3);
}

__global__ void split_transpose(const float* __restrict__ in, __nv_bfloat16* __restrict__ hi,
                                __nv_bfloat16* __restrict__ lo, int K, int N)
{
    __shared__ float t[32][33];
    const int n0 = blockIdx.x * 32, k0 = blockIdx.y * 32;
    const int tx = threadIdx.x, ty = threadIdx.y;
    #pragma unroll
    for (int r = 0; r < 4; r++)
        t[ty + r * 8][tx] = in[(size_t)(k0 + ty + r * 8) * N + n0 + tx];
    __syncthreads();
    #pragma unroll
    for (int r = 0; r < 4; r++) {
        int n = n0 + ty + r * 8;
        int k = k0 + tx;
        float v = t[tx][ty + r * 8];
        __nv_bfloat16 h = __float2bfloat16(v);
        __nv_bfloat16 l = __float2bfloat16(v - __bfloat162float(h));
        hi[(size_t)n * K + k] = h;
        lo[(size_t)n * K + k] = l;
    }
}

// ===================== bf16x3 tensor-core GEMM (unchanged from R3) =====================
#define STG 32768
#define GEMM_SMEM (3 * STG)

__global__ __launch_bounds__(256)
void gemm_bf16x3(const __nv_bfloat16* __restrict__ Ah, const __nv_bfloat16* __restrict__ Al,
                 const __nv_bfloat16* __restrict__ Bh, const __nv_bfloat16* __restrict__ Bl,
                 const float* __restrict__ bias, float* __restrict__ C, int N)
{
    extern __shared__ __align__(128) char smem[];
    const uint32_t sb = smem_u32(smem);
    const int tid = threadIdx.x, warp = tid >> 5, lane = tid & 31;
    const int wm = warp >> 1, wn = warp & 1;
    const int m0 = blockIdx.x * 128, n0 = blockIdx.y * 128;

    const char* srcs[4] = {
        (const char*)(Ah + (size_t)m0 * KDIM),
        (const char*)(Al + (size_t)m0 * KDIM),
        (const char*)(Bh + (size_t)n0 * KDIM),
        (const char*)(Bl + (size_t)n0 * KDIM)
    };

    const int ldrow0 = tid >> 2, ldc = tid & 3;
    const uint32_t dsw0 = swz64(ldrow0, ldc);
    const uint32_t dsw1 = swz64(ldrow0 + 64, ldc);

    auto load_stage = [&](int st, int kc) {
        uint32_t base = sb + st * STG;
        size_t kb = (size_t)kc * 64;
        #pragma unroll
        for (int mat = 0; mat < 4; mat++) {
            const char* s = srcs[mat];
            uint32_t d = base + mat * 8192;
            cp16(d + dsw0, s + (size_t)ldrow0 * 8192 + kb + ldc * 16);
            cp16(d + dsw1, s + (size_t)(ldrow0 + 64) * 8192 + kb + ldc * 16);
        }
    };

    const int g = lane >> 3, r = lane & 7;
    uint32_t offA[2][2], offB[4][2];
    #pragma unroll
    for (int mt = 0; mt < 2; mt++)
        #pragma unroll
        for (int ks = 0; ks < 2; ks++)
            offA[mt][ks] = swz64(wm * 32 + mt * 16 + (g & 1) * 8 + r, ks * 2 + (g >> 1));
    #pragma unroll
    for (int p = 0; p < 4; p++)
        #pragma unroll
        for (int ks = 0; ks < 2; ks++)
            offB[p][ks] = swz64(wn * 64 + p * 16 + (g >> 1) * 8 + r, ks * 2 + (g & 1));

    float acc[2][8][4];
    #pragma unroll
    for (int mt = 0; mt < 2; mt++)
        #pragma unroll
        for (int nt = 0; nt < 8; nt++)
            #pragma unroll
            for (int q = 0; q < 4; q++) acc[mt][nt][q] = 0.f;

    load_stage(0, 0); cp_commit();
    load_stage(1, 1); cp_commit();

    int st = 0;
    for (int i = 0; i < KITERS; i++) {
        cp_wait1();
        __syncthreads();
        if (i + 2 < KITERS) load_stage((st + 2) % 3, i + 2);
        cp_commit();

        uint32_t base = sb + st * STG;
        #pragma unroll
        for (int ks = 0; ks < 2; ks++) {
            uint32_t ah[2][4], al[2][4], bh[8][2], bl[8][2];
            #pragma unroll
            for (int mt = 0; mt < 2; mt++) {
                ldsm4(ah[mt], base + offA[mt][ks]);
                ldsm4(al[mt], base + 8192 + offA[mt][ks]);
            }
            #pragma unroll
            for (int p = 0; p < 4; p++) {
                uint32_t t4[4];
                ldsm4(t4, base + 16384 + offB[p][ks]);
                bh[2*p][0] = t4[0]; bh[2*p][1] = t4[1];
                bh[2*p+1][0] = t4[2]; bh[2*p+1][1] = t4[3];
                ldsm4(t4, base + 24576 + offB[p][ks]);
                bl[2*p][0] = t4[0]; bl[2*p][1] = t4[1];
                bl[2*p+1][0] = t4[2]; bl[2*p+1][1] = t4[3];
            }
            #pragma unroll
            for (int mt = 0; mt < 2; mt++)
                #pragma unroll
                for (int nt = 0; nt < 8; nt++) {
                    mma16816(acc[mt][nt], ah[mt], bh[nt]);
                    mma16816(acc[mt][nt], ah[mt], bl[nt]);
                    mma16816(acc[mt][nt], al[mt], bh[nt]);
                }
        }
        st = (st + 1) % 3;
    }

    #pragma unroll
    for (int mt = 0; mt < 2; mt++) {
        int row0 = m0 + wm * 32 + mt * 16 + (lane >> 2);
        #pragma unroll
        for (int nt = 0; nt < 8; nt++) {
            int col = n0 + wn * 64 + nt * 8 + (lane & 3) * 2;
            float bx = __ldg(bias + col), by = __ldg(bias + col + 1);
            float2 v0 = make_float2(acc[mt][nt][0] + bx, acc[mt][nt][1] + by);
            float2 v1 = make_float2(acc[mt][nt][2] + bx, acc[mt][nt][3] + by);
            *(float2*)&C[(size_t)row0 * N + col] = v0;
            *(float2*)&C[(size_t)(row0 + 8) * N + col] = v1;
        }
    }
}

// ---------------- LayerNorm + RoPE -> bf16 hi/lo Q,K,V [h][s][d] ----------
__global__ void ln_rope_kernel(const float* __restrict__ fused,
                               const float* __restrict__ qw, const float* __restrict__ qb,
                               const float* __restrict__ kw, const float* __restrict__ kb,
                               __nv_bfloat16* __restrict__ Qh, __nv_bfloat16* __restrict__ Ql,
                               __nv_bfloat16* __restrict__ Kh, __nv_bfloat16* __restrict__ Kl,
                               __nv_bfloat16* __restrict__ Vh, __nv_bfloat16* __restrict__ Vl)
{
    const int s = blockIdx.x;
    const int h = blockIdx.y;
    const int d = threadIdx.x;
    const int w = d >> 5;
    const int lane = d & 31;

    const float* base = fused + (size_t)s * QKV3 + h * (3 * HD);
    float q = base[d];
    float k = base[HD + d];
    float v = base[2 * HD + d];

    __shared__ float sh[2];

    auto bsum = [&](float x) -> float {
        #pragma unroll
        for (int o = 16; o; o >>= 1) x += __shfl_xor_sync(0xffffffffu, x, o);
        __syncthreads();
        if (lane == 0) sh[w] = x;
        __syncthreads();
        return sh[0] + sh[1];
    };

    float mu = bsum(q) * (1.f / HD);
    float dq = q - mu;
    float var = bsum(dq * dq) * (1.f / HD);
    float qn = dq * rsqrtf(var + EPS) * qw[d] + qb[d];

    mu = bsum(k) * (1.f / HD);
    float dk = k - mu;
    var = bsum(dk * dk) * (1.f / HD);
    float kn = dk * rsqrtf(var + EPS) * kw[d] + kb[d];

    float qo = __shfl_xor_sync(0xffffffffu, qn, 16);
    float ko = __shfl_xor_sync(0xffffffffu, kn, 16);
    if (d < ROT) {
        int f = d & 15;
        float invf = (float)pow(25000.0, -(double)f / 16.0);
        float ph = (float)s * invf;
        float c = cosf(ph);
        float si = sinf(ph);
        float sign = (d < 16) ? -1.f : 1.f;
        qn = qn * c + sign * qo * si;
        kn = kn * c + sign * ko * si;
    }
    qn *= 0.125f;   // fold 1/sqrt(HD) into Q (exact)

    size_t o = ((size_t)h * S + s) * HD + d;
    __nv_bfloat16 qh = __float2bfloat16(qn);
    __nv_bfloat16 kh = __float2bfloat16(kn);
    __nv_bfloat16 vh = __float2bfloat16(v);
    Qh[o] = qh; Ql[o] = __float2bfloat16(qn - __bfloat162float(qh));
    Kh[o] = kh; Kl[o] = __float2bfloat16(kn - __bfloat162float(kh));
    Vh[o] = vh; Vl[o] = __float2bfloat16(v - __bfloat162float(vh));
}

// ---------------- flash attention (tensor cores, bf16x2 splits) ------------
// grid (32, 64): (q-tile reversed, head). block 128 = 4 warps (16 q each).
// smem: Qh[8K] Ql[8K] | 2 stages x (Kh 8K, Kl 8K, Vh 8K, Vl 8K)
#define ATT_STG0  16384
#define ATT_STGSZ 32768
#define ATT_SMEM  (16384 + 2 * ATT_STGSZ)

__global__ __launch_bounds__(128)
void flash_attn(const __nv_bfloat16* __restrict__ Qh, const __nv_bfloat16* __restrict__ Ql,
                const __nv_bfloat16* __restrict__ Kh, const __nv_bfloat16* __restrict__ Kl,
                const __nv_bfloat16* __restrict__ Vh, const __nv_bfloat16* __restrict__ Vl,
                __nv_bfloat16* __restrict__ Oh, __nv_bfloat16* __restrict__ Ol)
{
    extern __shared__ __align__(128) char smem[];
    const uint32_t sb = smem_u32(smem);
    const int h = blockIdx.y;
    const int t = gridDim.x - 1 - blockIdx.x;     // big tiles first
    const int tid = threadIdx.x, warp = tid >> 5, lane = tid & 31;
    const int g = lane >> 3, r = lane & 7;

    const char* qhp = (const char*)(Qh + ((size_t)h * S + t * 64) * HD);
    const char* qlp = (const char*)(Ql + ((size_t)h * S + t * 64) * HD);
    const char* khp = (const char*)(Kh + (size_t)h * S * HD);
    const char* klp = (const char*)(Kl + (size_t)h * S * HD);
    const char* vhp = (const char*)(Vh + (size_t)h * S * HD);
    const char* vlp = (const char*)(Vl + (size_t)h * S * HD);

    // preload Q (hi+lo)
    for (int i = tid; i < 512; i += 128) {
        int row = i >> 3, c = i & 7;
        uint32_t o = swz128(row, c);
        cp16(sb + o, qhp + row * 128 + c * 16);
        cp16(sb + 8192 + o, qlp + row * 128 + c * 16);
    }
    auto load_kv = [&](int st, int kt) {
        uint32_t base = sb + ATT_STG0 + st * ATT_STGSZ;
        size_t gro = (size_t)kt * 64 * 128;
        for (int i = tid; i < 512; i += 128) {
            int row = i >> 3, c = i & 7;
            uint32_t o = swz128(row, c);
            size_t go = gro + row * 128 + c * 16;
            cp16(base + o,          khp + go);
            cp16(base + 8192 + o,   klp + go);
            cp16(base + 16384 + o,  vhp + go);
            cp16(base + 24576 + o,  vlp + go);
        }
    };
    load_kv(0, 0);
    cp_commit();

    uint32_t aQh[4][4], aQl[4][4];
    uint32_t offA[4];
    #pragma unroll
    for (int kc = 0; kc < 4; kc++)
        offA[kc] = swz128(warp * 16 + (g & 1) * 8 + r, kc * 2 + (g >> 1));

    float accO[8][4];
    #pragma unroll
    for (int nt = 0; nt < 8; nt++)
        #pragma unroll
        for (int c = 0; c < 4; c++) accO[nt][c] = 0.f;
    float m0 = -1e30f, m1 = -1e30f, l0 = 0.f, l1 = 0.f;

    int st = 0;
    for (int kt = 0; kt <= t; kt++) {
        __syncthreads();                       // prev compute done before overwrite
        if (kt + 1 <= t) load_kv(st ^ 1, kt + 1);
        cp_commit();
        cp_wait1();
        __syncthreads();

        if (kt == 0) {
            #pragma unroll
            for (int kc = 0; kc < 4; kc++) {
                ldsm4(aQh[kc], sb + offA[kc]);
                ldsm4(aQl[kc], sb + 8192 + offA[kc]);
            }
        }

        uint32_t base = sb + ATT_STG0 + st * ATT_STGSZ;

        // S = Q K^T
        float s[8][4];
        #pragma unroll
        for (int nt = 0; nt < 8; nt++)
            #pragma unroll
            for (int c = 0; c < 4; c++) s[nt][c] = 0.f;
        #pragma unroll
        for (int kc = 0; kc < 4; kc++) {
            #pragma unroll
            for (int p = 0; p < 4; p++) {
                uint32_t offb = swz128(p * 16 + (g >> 1) * 8 + r, kc * 2 + (g & 1));
                uint32_t th[4], tl[4];
                ldsm4(th, base + offb);
                ldsm4(tl, base + 8192 + offb);
                mma16816(s[2*p],   aQh[kc], th);
                mma16816(s[2*p+1], aQh[kc], th + 2);
                mma16816(s[2*p],   aQh[kc], tl);
                mma16816(s[2*p+1], aQh[kc], tl + 2);
                mma16816(s[2*p],   aQl[kc], th);
                mma16816(s[2*p+1], aQl[kc], th + 2);
            }
        }

        // causal mask on diagonal tile
        if (kt == t) {
            int q0loc = warp * 16 + (lane >> 2);
            #pragma unroll
            for (int nt = 0; nt < 8; nt++) {
                int kc0 = nt * 8 + (lane & 3) * 2;
                if (kc0 > q0loc)     s[nt][0] = -1e30f;
                if (kc0 + 1 > q0loc) s[nt][1] = -1e30f;
                if (kc0 > q0loc + 8)     s[nt][2] = -1e30f;
                if (kc0 + 1 > q0loc + 8) s[nt][3] = -1e30f;
            }
        }

        // online softmax
        float mx0 = -1e30f, mx1 = -1e30f;
        #pragma unroll
        for (int nt = 0; nt < 8; nt++) {
            mx0 = fmaxf(mx0, fmaxf(s[nt][0], s[nt][1]));
            mx1 = fmaxf(mx1, fmaxf(s[nt][2], s[nt][3]));
        }
        mx0 = fmaxf(mx0, __shfl_xor_sync(0xffffffffu, mx0, 1));
        mx0 = fmaxf(mx0, __shfl_xor_sync(0xffffffffu, mx0, 2));
        mx1 = fmaxf(mx1, __shfl_xor_sync(0xffffffffu, mx1, 1));
        mx1 = fmaxf(mx1, __shfl_xor_sync(0xffffffffu, mx1, 2));
        float mn0 = fmaxf(m0, mx0), mn1 = fmaxf(m1, mx1);
        float corr0 = __expf(m0 - mn0), corr1 = __expf(m1 - mn1);
        m0 = mn0; m1 = mn1;
        l0 *= corr0; l1 *= corr1;
        #pragma unroll
        for (int nt = 0; nt < 8; nt++) {
            accO[nt][0] *= corr0; accO[nt][1] *= corr0;
            accO[nt][2] *= corr1; accO[nt][3] *= corr1;
        }

        uint32_t Ph0[8], Ph1[8], Pl0[8], Pl1[8];
        #pragma unroll
        for (int nt = 0; nt < 8; nt++) {
            float p0 = __expf(s[nt][0] - m0);
            float p1 = __expf(s[nt][1] - m0);
            float p2 = __expf(s[nt][2] - m1);
            float p3 = __expf(s[nt][3] - m1);
            l0 += p0 + p1; l1 += p2 + p3;
            __nv_bfloat162 h01 = __floats2bfloat162_rn(p0, p1);
            __nv_bfloat162 h23 = __floats2bfloat162_rn(p2, p3);
            __nv_bfloat162 q01 = __floats2bfloat162_rn(p0 - __low2float(h01), p1 - __high2float(h01));
            __nv_bfloat162 q23 = __floats2bfloat162_rn(p2 - __low2float(h23), p3 - __high2float(h23));
            Ph0[nt] = *(uint32_t*)&h01; Ph1[nt] = *(uint32_t*)&h23;
            Pl0[nt] = *(uint32_t*)&q01; Pl1[nt] = *(uint32_t*)&q23;
        }

        // O += P V   (V via ldmatrix.trans)
        #pragma unroll
        for (int kc = 0; kc < 4; kc++) {
            uint32_t aPh[4] = {Ph0[2*kc], Ph1[2*kc], Ph0[2*kc+1], Ph1[2*kc+1]};
            uint32_t aPl[4] = {Pl0[2*kc], Pl1[2*kc], Pl0[2*kc+1], Pl1[2*kc+1]};
            #pragma unroll
            for (int p = 0; p < 4; p++) {
                uint32_t offv = swz128(kc * 16 + (g & 1) * 8 + r, p * 2 + (g >> 1));
                uint32_t vh[4], vl[4];
                ldsm4t(vh, base + 16384 + offv);
                ldsm4t(vl, base + 24576 + offv);
                mma16816(accO[2*p],   aPh, vh);
                mma16816(accO[2*p+1], aPh, vh + 2);
                mma16816(accO[2*p],   aPh, vl);
                mma16816(accO[2*p+1], aPh, vl + 2);
                mma16816(accO[2*p],   aPl, vh);
                mma16816(accO[2*p+1], aPl, vh + 2);
            }
        }
        st ^= 1;
    }

    // epilogue: normalize, split to bf16 hi/lo, write [s, h*64+d]
    l0 += __shfl_xor_sync(0xffffffffu, l0, 1);
    l0 += __shfl_xor_sync(0xffffffffu, l0, 2);
    l1 += __shfl_xor_sync(0xffffffffu, l1, 1);
    l1 += __shfl_xor_sync(0xffffffffu, l1, 2);
    float inv0 = 1.f / l0, inv1 = 1.f / l1;
    int r0 = t * 64 + warp * 16 + (lane >> 2);
    #pragma unroll
    for (int nt = 0; nt < 8; nt++) {
        int col = h * 64 + nt * 8 + (lane & 3) * 2;
        float o0 = accO[nt][0] * inv0, o1 = accO[nt][1] * inv0;
        float o2 = accO[nt][2] * inv1, o3 = accO[nt][3] * inv1;
        __nv_bfloat162 h01 = __floats2bfloat162_rn(o0, o1);
        __nv_bfloat162 h23 = __floats2bfloat162_rn(o2, o3);
        __nv_bfloat162 q01 = __floats2bfloat162_rn(o0 - __low2float(h01), o1 - __high2float(h01));
        __nv_bfloat162 q23 = __floats2bfloat162_rn(o2 - __low2float(h23), o3 - __high2float(h23));
        *(__nv_bfloat162*)&Oh[(size_t)r0 * HID + col] = h01;
        *(__nv_bfloat162*)&Ol[(size_t)r0 * HID + col] = q01;
        *(__nv_bfloat162*)&Oh[(size_t)(r0 + 8) * HID + col] = h23;
        *(__nv_bfloat162*)&Ol[(size_t)(r0 + 8) * HID + col] = q23;
    }
}

// ---------------- launch ---------------------------------------------------
extern "C" void kernel_launch(void* const* d_in, const int* in_sizes, int n_in,
                              void* d_out, int out_size)
{
    const float* hs    = (const float*)d_in[0];
    const float* Wqkv  = (const float*)d_in[3];
    const float* bqkv  = (const float*)d_in[4];
    const float* Wd    = (const float*)d_in[5];
    const float* bd    = (const float*)d_in[6];
    const float* qw    = (const float*)d_in[7];
    const float* qb    = (const float*)d_in[8];
    const float* kw    = (const float*)d_in[9];
    const float* kb    = (const float*)d_in[10];
    float* out = (float*)d_out;

    float* fused;
    __nv_bfloat16 *Ahp, *Alp, *Bqh, *Bql, *Bdh, *Bdl;
    __nv_bfloat16 *Qhp, *Qlp, *Khp, *Klp, *Vhp, *Vlp;
    cudaGetSymbolAddress((void**)&fused, g_fused);
    cudaGetSymbolAddress((void**)&Ahp,   g_Ah);
    cudaGetSymbolAddress((void**)&Alp,   g_Al);
    cudaGetSymbolAddress((void**)&Bqh,   g_Bqh);
    cudaGetSymbolAddress((void**)&Bql,   g_Bql);
    cudaGetSymbolAddress((void**)&Bdh,   g_Bdh);
    cudaGetSymbolAddress((void**)&Bdl,   g_Bdl);
    cudaGetSymbolAddress((void**)&Qhp,   g_Qh);
    cudaGetSymbolAddress((void**)&Qlp,   g_Ql);
    cudaGetSymbolAddress((void**)&Khp,   g_Kh);
    cudaGetSymbolAddress((void**)&Klp,   g_Kl);
    cudaGetSymbolAddress((void**)&Vhp,   g_Vh);
    cudaGetSymbolAddress((void**)&Vlp,   g_Vl);

    static int attr_set = 0;
    if (!attr_set) {
        cudaFuncSetAttribute(gemm_bf16x3, cudaFuncAttributeMaxDynamicSharedMemorySize, GEMM_SMEM);
        cudaFuncSetAttribute(flash_attn, cudaFuncAttributeMaxDynamicSharedMemorySize, ATT_SMEM);
        attr_set = 1;
    }

    // 0) conversions
    split_rows<<<(S * HID / 4 + 255) / 256, 256>>>(hs, Ahp, Alp, S * HID / 4);
    split_transpose<<<dim3(QKV3 / 32, HID / 32), dim3(32, 8)>>>(Wqkv, Bqh, Bql, KDIM, QKV3);
    split_transpose<<<dim3(HID / 32, HID / 32), dim3(32, 8)>>>(Wd, Bdh, Bdl, KDIM, HID);

    // 1) QKV GEMM
    gemm_bf16x3<<<dim3(S / 128, QKV3 / 128), 256, GEMM_SMEM>>>(Ahp, Alp, Bqh, Bql, bqkv, fused, QKV3);

    // 2) LN + RoPE -> bf16 hi/lo Q,K,V
    ln_rope_kernel<<<dim3(S, NH), HD>>>(fused, qw, qb, kw, kb, Qhp, Qlp, Khp, Klp, Vhp, Vlp);

    // 3) flash attention -> bf16 hi/lo activations for dense GEMM
    flash_attn<<<dim3(S / 64, NH), 128, ATT_SMEM>>>(Qhp, Qlp, Khp, Klp, Vhp, Vlp, Ahp, Alp);

    // 4) dense GEMM -> out
    gemm_bf16x3<<<dim3(S / 128, HID / 128), 256, GEMM_SMEM>>>(Ahp, Alp, Bdh, Bdl, bd, out, HID);
}

// round 6
// speedup vs baseline: 3.9364x; 1.0997x over previous
#include <cuda_runtime.h>
#include <cuda_bf16.h>
#include <math.h>
#include <stdint.h>

// Problem constants
#define S    2048
#define HID  4096
#define NH   64
#define HD   64
#define ROT  32
#define QKV3 12288   // 3*HID
#define EPS  1e-5f
#define KDIM 4096
#define BKB  32
#define KITERS (KDIM / BKB)      // 128

// ---------------- scratch (device globals) ----------------
__device__ float g_fused[S * QKV3];
__device__ __nv_bfloat16 g_Ah[S * HID];
__device__ __nv_bfloat16 g_Al[S * HID];
__device__ __nv_bfloat16 g_Bqh[QKV3 * HID];
__device__ __nv_bfloat16 g_Bql[QKV3 * HID];
__device__ __nv_bfloat16 g_Bdh[HID * HID];
__device__ __nv_bfloat16 g_Bdl[HID * HID];
__device__ __nv_bfloat16 g_Qh[NH * S * HD];
__device__ __nv_bfloat16 g_Ql[NH * S * HD];
__device__ __nv_bfloat16 g_Kh[NH * S * HD];
__device__ __nv_bfloat16 g_Kl[NH * S * HD];
__device__ __nv_bfloat16 g_Vh[NH * S * HD];
__device__ __nv_bfloat16 g_Vl[NH * S * HD];

// ===================== PTX helpers =====================
__device__ __forceinline__ uint32_t smem_u32(const void* p) {
    uint32_t a;
    asm("{ .reg .u64 t; cvta.to.shared.u64 t, %1; cvt.u32.u64 %0, t; }" : "=r"(a) : "l"(p));
    return a;
}
__device__ __forceinline__ void cp16(uint32_t dst, const void* src) {
    asm volatile("cp.async.cg.shared.global [%0], [%1], 16;\n" :: "r"(dst), "l"(src));
}
__device__ __forceinline__ void cp_commit() { asm volatile("cp.async.commit_group;\n" ::: "memory"); }
__device__ __forceinline__ void cp_wait1()  { asm volatile("cp.async.wait_group 1;\n" ::: "memory"); }

__device__ __forceinline__ void ldsm4(uint32_t* r, uint32_t addr) {
    asm volatile("ldmatrix.sync.aligned.m8n8.x4.shared.b16 {%0,%1,%2,%3}, [%4];"
                 : "=r"(r[0]), "=r"(r[1]), "=r"(r[2]), "=r"(r[3]) : "r"(addr));
}
__device__ __forceinline__ void ldsm4t(uint32_t* r, uint32_t addr) {
    asm volatile("ldmatrix.sync.aligned.m8n8.x4.trans.shared.b16 {%0,%1,%2,%3}, [%4];"
                 : "=r"(r[0]), "=r"(r[1]), "=r"(r[2]), "=r"(r[3]) : "r"(addr));
}
__device__ __forceinline__ void mma16816(float* d, const uint32_t* a, const uint32_t* b) {
    asm volatile("mma.sync.aligned.m16n8k16.row.col.f32.bf16.bf16.f32 "
                 "{%0,%1,%2,%3}, {%4,%5,%6,%7}, {%8,%9}, {%0,%1,%2,%3};"
                 : "+f"(d[0]), "+f"(d[1]), "+f"(d[2]), "+f"(d[3])
                 : "r"(a[0]), "r"(a[1]), "r"(a[2]), "r"(a[3]), "r"(b[0]), "r"(b[1]));
}

__device__ __forceinline__ uint32_t swz64(int row, int kc) {
    return (uint32_t)(row * 64 + ((kc ^ ((row >> 1) & 3)) << 4));
}
__device__ __forceinline__ uint32_t swz128(int row, int c) {
    return (uint32_t)(row * 128 + ((c ^ (row & 7)) << 4));
}

// fast exp2 on fma/alu pipes (input already in log2 domain); rel err ~2.4e-6
__device__ __forceinline__ float fexp2(float x) {
    x = fmaxf(x, -126.0f);
    float t = x + 12582912.0f;                 // round-to-nearest int (magic)
    int   n = __float_as_int(t) - 0x4B400000;  // = round(x)
    float f = x - (t - 12582912.0f);           // f in [-0.5, 0.5]
    float p =      1.3333558146e-3f;
    p = fmaf(p, f, 9.6181291076e-3f);
    p = fmaf(p, f, 5.5504108665e-2f);
    p = fmaf(p, f, 2.4022650696e-1f);
    p = fmaf(p, f, 6.9314718056e-1f);
    p = fmaf(p, f, 1.0f);
    return __int_as_float(__float_as_int(p) + (n << 23));
}

// ===================== split / transpose conversion kernels =====================
__global__ void split_rows(const float* __restrict__ in, __nv_bfloat16* __restrict__ hi,
                           __nv_bfloat16* __restrict__ lo, int n4)
{
    int i = blockIdx.x * blockDim.x + threadIdx.x;
    if (i >= n4) return;
    float4 v = ((const float4*)in)[i];
    __nv_bfloat16 h0 = __float2bfloat16(v.x);
    __nv_bfloat16 h1 = __float2bfloat16(v.y);
    __nv_bfloat16 h2 = __float2bfloat16(v.z);
    __nv_bfloat16 h3 = __float2bfloat16(v.w);
    __nv_bfloat16 l0 = __float2bfloat16(v.x - __bfloat162float(h0));
    __nv_bfloat16 l1 = __float2bfloat16(v.y - __bfloat162float(h1));
    __nv_bfloat16 l2 = __float2bfloat16(v.z - __bfloat162float(h2));
    __nv_bfloat16 l3 = __float2bfloat16(v.w - __bfloat162float(h3));
    ((__nv_bfloat162*)hi)[2 * i]     = __nv_bfloat162(h0, h1);
    ((__nv_bfloat162*)hi)[2 * i + 1] = __nv_bfloat162(h2, h3);
    ((__nv_bfloat162*)lo)[2 * i]     = __nv_bfloat162(l0, l1);
    ((__nv_bfloat162*)lo)[2 * i + 1] = __nv_bfloat162(l2, l3);
}

__global__ void split_transpose(const float* __restrict__ in, __nv_bfloat16* __restrict__ hi,
                                __nv_bfloat16* __restrict__ lo, int K, int N)
{
    __shared__ float t[32][33];
    const int n0 = blockIdx.x * 32, k0 = blockIdx.y * 32;
    const int tx = threadIdx.x, ty = threadIdx.y;
    #pragma unroll
    for (int r = 0; r < 4; r++)
        t[ty + r * 8][tx] = in[(size_t)(k0 + ty + r * 8) * N + n0 + tx];
    __syncthreads();
    #pragma unroll
    for (int r = 0; r < 4; r++) {
        int n = n0 + ty + r * 8;
        int k = k0 + tx;
        float v = t[tx][ty + r * 8];
        __nv_bfloat16 h = __float2bfloat16(v);
        __nv_bfloat16 l = __float2bfloat16(v - __bfloat162float(h));
        hi[(size_t)n * K + k] = h;
        lo[(size_t)n * K + k] = l;
    }
}

// ===================== bf16x3 tensor-core GEMM =====================
#define STG 32768
#define GEMM_SMEM (3 * STG)

__global__ __launch_bounds__(256, 2)
void gemm_bf16x3(const __nv_bfloat16* __restrict__ Ah, const __nv_bfloat16* __restrict__ Al,
                 const __nv_bfloat16* __restrict__ Bh, const __nv_bfloat16* __restrict__ Bl,
                 const float* __restrict__ bias, float* __restrict__ C, int N)
{
    extern __shared__ __align__(128) char smem[];
    const uint32_t sb = smem_u32(smem);
    const int tid = threadIdx.x, warp = tid >> 5, lane = tid & 31;
    const int wm = warp >> 1, wn = warp & 1;
    const int m0 = blockIdx.x * 128, n0 = blockIdx.y * 128;

    const char* srcs[4] = {
        (const char*)(Ah + (size_t)m0 * KDIM),
        (const char*)(Al + (size_t)m0 * KDIM),
        (const char*)(Bh + (size_t)n0 * KDIM),
        (const char*)(Bl + (size_t)n0 * KDIM)
    };

    const int ldrow0 = tid >> 2, ldc = tid & 3;
    const uint32_t dsw0 = swz64(ldrow0, ldc);
    const uint32_t dsw1 = swz64(ldrow0 + 64, ldc);

    auto load_stage = [&](int st, int kc) {
        uint32_t base = sb + st * STG;
        size_t kb = (size_t)kc * 64;
        #pragma unroll
        for (int mat = 0; mat < 4; mat++) {
            const char* s = srcs[mat];
            uint32_t d = base + mat * 8192;
            cp16(d + dsw0, s + (size_t)ldrow0 * 8192 + kb + ldc * 16);
            cp16(d + dsw1, s + (size_t)(ldrow0 + 64) * 8192 + kb + ldc * 16);
        }
    };

    const int g = lane >> 3, r = lane & 7;
    uint32_t offA[2][2], offB[4][2];
    #pragma unroll
    for (int mt = 0; mt < 2; mt++)
        #pragma unroll
        for (int ks = 0; ks < 2; ks++)
            offA[mt][ks] = swz64(wm * 32 + mt * 16 + (g & 1) * 8 + r, ks * 2 + (g >> 1));
    #pragma unroll
    for (int p = 0; p < 4; p++)
        #pragma unroll
        for (int ks = 0; ks < 2; ks++)
            offB[p][ks] = swz64(wn * 64 + p * 16 + (g >> 1) * 8 + r, ks * 2 + (g & 1));

    float acc[2][8][4];
    #pragma unroll
    for (int mt = 0; mt < 2; mt++)
        #pragma unroll
        for (int nt = 0; nt < 8; nt++)
            #pragma unroll
            for (int q = 0; q < 4; q++) acc[mt][nt][q] = 0.f;

    load_stage(0, 0); cp_commit();
    load_stage(1, 1); cp_commit();

    int st = 0;
    for (int i = 0; i < KITERS; i++) {
        cp_wait1();
        __syncthreads();
        if (i + 2 < KITERS) load_stage((st + 2) % 3, i + 2);
        cp_commit();

        uint32_t base = sb + st * STG;
        #pragma unroll
        for (int ks = 0; ks < 2; ks++) {
            uint32_t ah[2][4], al[2][4], bh[8][2], bl[8][2];
            #pragma unroll
            for (int mt = 0; mt < 2; mt++) {
                ldsm4(ah[mt], base + offA[mt][ks]);
                ldsm4(al[mt], base + 8192 + offA[mt][ks]);
            }
            #pragma unroll
            for (int p = 0; p < 4; p++) {
                uint32_t t4[4];
                ldsm4(t4, base + 16384 + offB[p][ks]);
                bh[2*p][0] = t4[0]; bh[2*p][1] = t4[1];
                bh[2*p+1][0] = t4[2]; bh[2*p+1][1] = t4[3];
                ldsm4(t4, base + 24576 + offB[p][ks]);
                bl[2*p][0] = t4[0]; bl[2*p][1] = t4[1];
                bl[2*p+1][0] = t4[2]; bl[2*p+1][1] = t4[3];
            }
            #pragma unroll
            for (int mt = 0; mt < 2; mt++)
                #pragma unroll
                for (int nt = 0; nt < 8; nt++) {
                    mma16816(acc[mt][nt], ah[mt], bh[nt]);
                    mma16816(acc[mt][nt], ah[mt], bl[nt]);
                    mma16816(acc[mt][nt], al[mt], bh[nt]);
                }
        }
        st = (st + 1) % 3;
    }

    #pragma unroll
    for (int mt = 0; mt < 2; mt++) {
        int row0 = m0 + wm * 32 + mt * 16 + (lane >> 2);
        #pragma unroll
        for (int nt = 0; nt < 8; nt++) {
            int col = n0 + wn * 64 + nt * 8 + (lane & 3) * 2;
            float bx = __ldg(bias + col), by = __ldg(bias + col + 1);
            float2 v0 = make_float2(acc[mt][nt][0] + bx, acc[mt][nt][1] + by);
            float2 v1 = make_float2(acc[mt][nt][2] + bx, acc[mt][nt][3] + by);
            *(float2*)&C[(size_t)row0 * N + col] = v0;
            *(float2*)&C[(size_t)(row0 + 8) * N + col] = v1;
        }
    }
}

// ---------------- LayerNorm + RoPE -> bf16 hi/lo Q,K,V [h][s][d] ----------
// Q is scaled by (1/sqrt(HD)) * log2(e) so attention logits are in log2 domain.
__global__ void ln_rope_kernel(const float* __restrict__ fused,
                               const float* __restrict__ qw, const float* __restrict__ qb,
                               const float* __restrict__ kw, const float* __restrict__ kb,
                               __nv_bfloat16* __restrict__ Qh, __nv_bfloat16* __restrict__ Ql,
                               __nv_bfloat16* __restrict__ Kh, __nv_bfloat16* __restrict__ Kl,
                               __nv_bfloat16* __restrict__ Vh, __nv_bfloat16* __restrict__ Vl)
{
    const int s = blockIdx.x;
    const int h = blockIdx.y;
    const int d = threadIdx.x;
    const int w = d >> 5;
    const int lane = d & 31;

    const float* base = fused + (size_t)s * QKV3 + h * (3 * HD);
    float q = base[d];
    float k = base[HD + d];
    float v = base[2 * HD + d];

    __shared__ float sh[2];

    auto bsum = [&](float x) -> float {
        #pragma unroll
        for (int o = 16; o; o >>= 1) x += __shfl_xor_sync(0xffffffffu, x, o);
        __syncthreads();
        if (lane == 0) sh[w] = x;
        __syncthreads();
        return sh[0] + sh[1];
    };

    float mu = bsum(q) * (1.f / HD);
    float dq = q - mu;
    float var = bsum(dq * dq) * (1.f / HD);
    float qn = dq * rsqrtf(var + EPS) * qw[d] + qb[d];

    mu = bsum(k) * (1.f / HD);
    float dk = k - mu;
    var = bsum(dk * dk) * (1.f / HD);
    float kn = dk * rsqrtf(var + EPS) * kw[d] + kb[d];

    float qo = __shfl_xor_sync(0xffffffffu, qn, 16);
    float ko = __shfl_xor_sync(0xffffffffu, kn, 16);
    if (d < ROT) {
        int f = d & 15;
        float invf = (float)pow(25000.0, -(double)f / 16.0);
        float ph = (float)s * invf;
        float c = cosf(ph);
        float si = sinf(ph);
        float sign = (d < 16) ? -1.f : 1.f;
        qn = qn * c + sign * qo * si;
        kn = kn * c + sign * ko * si;
    }
    qn *= 0.125f * 1.4426950408889634f;   // 1/sqrt(HD) * log2(e)

    size_t o = ((size_t)h * S + s) * HD + d;
    __nv_bfloat16 qh = __float2bfloat16(qn);
    __nv_bfloat16 kh = __float2bfloat16(kn);
    __nv_bfloat16 vh = __float2bfloat16(v);
    Qh[o] = qh; Ql[o] = __float2bfloat16(qn - __bfloat162float(qh));
    Kh[o] = kh; Kl[o] = __float2bfloat16(kn - __bfloat162float(kh));
    Vh[o] = vh; Vl[o] = __float2bfloat16(v - __bfloat162float(vh));
}

// ---------------- flash attention (tensor cores, log2-domain softmax) ------
#define ATT_STG0  16384
#define ATT_STGSZ 32768
#define ATT_SMEM  (16384 + 2 * ATT_STGSZ)

__global__ __launch_bounds__(128)
void flash_attn(const __nv_bfloat16* __restrict__ Qh, const __nv_bfloat16* __restrict__ Ql,
                const __nv_bfloat16* __restrict__ Kh, const __nv_bfloat16* __restrict__ Kl,
                const __nv_bfloat16* __restrict__ Vh, const __nv_bfloat16* __restrict__ Vl,
                __nv_bfloat16* __restrict__ Oh, __nv_bfloat16* __restrict__ Ol)
{
    extern __shared__ __align__(128) char smem[];
    const uint32_t sb = smem_u32(smem);
    const int h = blockIdx.y;
    const int t = gridDim.x - 1 - blockIdx.x;
    const int tid = threadIdx.x, warp = tid >> 5, lane = tid & 31;
    const int g = lane >> 3, r = lane & 7;

    const char* qhp = (const char*)(Qh + ((size_t)h * S + t * 64) * HD);
    const char* qlp = (const char*)(Ql + ((size_t)h * S + t * 64) * HD);
    const char* khp = (const char*)(Kh + (size_t)h * S * HD);
    const char* klp = (const char*)(Kl + (size_t)h * S * HD);
    const char* vhp = (const char*)(Vh + (size_t)h * S * HD);
    const char* vlp = (const char*)(Vl + (size_t)h * S * HD);

    for (int i = tid; i < 512; i += 128) {
        int row = i >> 3, c = i & 7;
        uint32_t o = swz128(row, c);
        cp16(sb + o, qhp + row * 128 + c * 16);
        cp16(sb + 8192 + o, qlp + row * 128 + c * 16);
    }
    auto load_kv = [&](int st, int kt) {
        uint32_t base = sb + ATT_STG0 + st * ATT_STGSZ;
        size_t gro = (size_t)kt * 64 * 128;
        for (int i = tid; i < 512; i += 128) {
            int row = i >> 3, c = i & 7;
            uint32_t o = swz128(row, c);
            size_t go = gro + row * 128 + c * 16;
            cp16(base + o,          khp + go);
            cp16(base + 8192 + o,   klp + go);
            cp16(base + 16384 + o,  vhp + go);
            cp16(base + 24576 + o,  vlp + go);
        }
    };
    load_kv(0, 0);
    cp_commit();

    uint32_t aQh[4][4], aQl[4][4];
    uint32_t offA[4];
    #pragma unroll
    for (int kc = 0; kc < 4; kc++)
        offA[kc] = swz128(warp * 16 + (g & 1) * 8 + r, kc * 2 + (g >> 1));

    float accO[8][4];
    #pragma unroll
    for (int nt = 0; nt < 8; nt++)
        #pragma unroll
        for (int c = 0; c < 4; c++) accO[nt][c] = 0.f;
    float m0 = -1e30f, m1 = -1e30f, l0 = 0.f, l1 = 0.f;

    int st = 0;
    for (int kt = 0; kt <= t; kt++) {
        __syncthreads();
        if (kt + 1 <= t) load_kv(st ^ 1, kt + 1);
        cp_commit();
        cp_wait1();
        __syncthreads();

        if (kt == 0) {
            #pragma unroll
            for (int kc = 0; kc < 4; kc++) {
                ldsm4(aQh[kc], sb + offA[kc]);
                ldsm4(aQl[kc], sb + 8192 + offA[kc]);
            }
        }

        uint32_t base = sb + ATT_STG0 + st * ATT_STGSZ;

        float s[8][4];
        #pragma unroll
        for (int nt = 0; nt < 8; nt++)
            #pragma unroll
            for (int c = 0; c < 4; c++) s[nt][c] = 0.f;
        #pragma unroll
        for (int kc = 0; kc < 4; kc++) {
            #pragma unroll
            for (int p = 0; p < 4; p++) {
                uint32_t offb = swz128(p * 16 + (g >> 1) * 8 + r, kc * 2 + (g & 1));
                uint32_t th[4], tl[4];
                ldsm4(th, base + offb);
                ldsm4(tl, base + 8192 + offb);
                mma16816(s[2*p],   aQh[kc], th);
                mma16816(s[2*p+1], aQh[kc], th + 2);
                mma16816(s[2*p],   aQh[kc], tl);
                mma16816(s[2*p+1], aQh[kc], tl + 2);
                mma16816(s[2*p],   aQl[kc], th);
                mma16816(s[2*p+1], aQl[kc], th + 2);
            }
        }

        if (kt == t) {
            int q0loc = warp * 16 + (lane >> 2);
            #pragma unroll
            for (int nt = 0; nt < 8; nt++) {
                int kc0 = nt * 8 + (lane & 3) * 2;
                if (kc0 > q0loc)     s[nt][0] = -1e30f;
                if (kc0 + 1 > q0loc) s[nt][1] = -1e30f;
                if (kc0 > q0loc + 8)     s[nt][2] = -1e30f;
                if (kc0 + 1 > q0loc + 8) s[nt][3] = -1e30f;
            }
        }

        float mx0 = -1e30f, mx1 = -1e30f;
        #pragma unroll
        for (int nt = 0; nt < 8; nt++) {
            mx0 = fmaxf(mx0, fmaxf(s[nt][0], s[nt][1]));
            mx1 = fmaxf(mx1, fmaxf(s[nt][2], s[nt][3]));
        }
        mx0 = fmaxf(mx0, __shfl_xor_sync(0xffffffffu, mx0, 1));
        mx0 = fmaxf(mx0, __shfl_xor_sync(0xffffffffu, mx0, 2));
        mx1 = fmaxf(mx1, __shfl_xor_sync(0xffffffffu, mx1, 1));
        mx1 = fmaxf(mx1, __shfl_xor_sync(0xffffffffu, mx1, 2));
        float mn0 = fmaxf(m0, mx0), mn1 = fmaxf(m1, mx1);
        float corr0 = fexp2(m0 - mn0), corr1 = fexp2(m1 - mn1);
        m0 = mn0; m1 = mn1;
        l0 *= corr0; l1 *= corr1;
        #pragma unroll
        for (int nt = 0; nt < 8; nt++) {
            accO[nt][0] *= corr0; accO[nt][1] *= corr0;
            accO[nt][2] *= corr1; accO[nt][3] *= corr1;
        }

        uint32_t Ph0[8], Ph1[8], Pl0[8], Pl1[8];
        #pragma unroll
        for (int nt = 0; nt < 8; nt++) {
            float p0 = fexp2(s[nt][0] - m0);
            float p1 = fexp2(s[nt][1] - m0);
            float p2 = fexp2(s[nt][2] - m1);
            float p3 = fexp2(s[nt][3] - m1);
            l0 += p0 + p1; l1 += p2 + p3;
            __nv_bfloat162 h01 = __floats2bfloat162_rn(p0, p1);
            __nv_bfloat162 h23 = __floats2bfloat162_rn(p2, p3);
            __nv_bfloat162 q01 = __floats2bfloat162_rn(p0 - __low2float(h01), p1 - __high2float(h01));
            __nv_bfloat162 q23 = __floats2bfloat162_rn(p2 - __low2float(h23), p3 - __high2float(h23));
            Ph0[nt] = *(uint32_t*)&h01; Ph1[nt] = *(uint32_t*)&h23;
            Pl0[nt] = *(uint32_t*)&q01; Pl1[nt] = *(uint32_t*)&q23;
        }

        #pragma unroll
        for (int kc = 0; kc < 4; kc++) {
            uint32_t aPh[4] = {Ph0[2*kc], Ph1[2*kc], Ph0[2*kc+1], Ph1[2*kc+1]};
            uint32_t aPl[4] = {Pl0[2*kc], Pl1[2*kc], Pl0[2*kc+1], Pl1[2*kc+1]};
            #pragma unroll
            for (int p = 0; p < 4; p++) {
                uint32_t offv = swz128(kc * 16 + (g & 1) * 8 + r, p * 2 + (g >> 1));
                uint32_t vh[4], vl[4];
                ldsm4t(vh, base + 16384 + offv);
                ldsm4t(vl, base + 24576 + offv);
                mma16816(accO[2*p],   aPh, vh);
                mma16816(accO[2*p+1], aPh, vh + 2);
                mma16816(accO[2*p],   aPh, vl);
                mma16816(accO[2*p+1], aPh, vl + 2);
                mma16816(accO[2*p],   aPl, vh);
                mma16816(accO[2*p+1], aPl, vh + 2);
            }
        }
        st ^= 1;
    }

    l0 += __shfl_xor_sync(0xffffffffu, l0, 1);
    l0 += __shfl_xor_sync(0xffffffffu, l0, 2);
    l1 += __shfl_xor_sync(0xffffffffu, l1, 1);
    l1 += __shfl_xor_sync(0xffffffffu, l1, 2);
    float inv0 = 1.f / l0, inv1 = 1.f / l1;
    int r0 = t * 64 + warp * 16 + (lane >> 2);
    #pragma unroll
    for (int nt = 0; nt < 8; nt++) {
        int col = h * 64 + nt * 8 + (lane & 3) * 2;
        float o0 = accO[nt][0] * inv0, o1 = accO[nt][1] * inv0;
        float o2 = accO[nt][2] * inv1, o3 = accO[nt][3] * inv1;
        __nv_bfloat162 h01 = __floats2bfloat162_rn(o0, o1);
        __nv_bfloat162 h23 = __floats2bfloat162_rn(o2, o3);
        __nv_bfloat162 q01 = __floats2bfloat162_rn(o0 - __low2float(h01), o1 - __high2float(h01));
        __nv_bfloat162 q23 = __floats2bfloat162_rn(o2 - __low2float(h23), o3 - __high2float(h23));
        *(__nv_bfloat162*)&Oh[(size_t)r0 * HID + col] = h01;
        *(__nv_bfloat162*)&Ol[(size_t)r0 * HID + col] = q01;
        *(__nv_bfloat162*)&Oh[(size_t)(r0 + 8) * HID + col] = h23;
        *(__nv_bfloat162*)&Ol[(size_t)(r0 + 8) * HID + col] = q23;
    }
}

// ---------------- launch ---------------------------------------------------
extern "C" void kernel_launch(void* const* d_in, const int* in_sizes, int n_in,
                              void* d_out, int out_size)
{
    const float* hs    = (const float*)d_in[0];
    const float* Wqkv  = (const float*)d_in[3];
    const float* bqkv  = (const float*)d_in[4];
    const float* Wd    = (const float*)d_in[5];
    const float* bd    = (const float*)d_in[6];
    const float* qw    = (const float*)d_in[7];
    const float* qb    = (const float*)d_in[8];
    const float* kw    = (const float*)d_in[9];
    const float* kb    = (const float*)d_in[10];
    float* out = (float*)d_out;

    float* fused;
    __nv_bfloat16 *Ahp, *Alp, *Bqh, *Bql, *Bdh, *Bdl;
    __nv_bfloat16 *Qhp, *Qlp, *Khp, *Klp, *Vhp, *Vlp;
    cudaGetSymbolAddress((void**)&fused, g_fused);
    cudaGetSymbolAddress((void**)&Ahp,   g_Ah);
    cudaGetSymbolAddress((void**)&Alp,   g_Al);
    cudaGetSymbolAddress((void**)&Bqh,   g_Bqh);
    cudaGetSymbolAddress((void**)&Bql,   g_Bql);
    cudaGetSymbolAddress((void**)&Bdh,   g_Bdh);
    cudaGetSymbolAddress((void**)&Bdl,   g_Bdl);
    cudaGetSymbolAddress((void**)&Qhp,   g_Qh);
    cudaGetSymbolAddress((void**)&Qlp,   g_Ql);
    cudaGetSymbolAddress((void**)&Khp,   g_Kh);
    cudaGetSymbolAddress((void**)&Klp,   g_Kl);
    cudaGetSymbolAddress((void**)&Vhp,   g_Vh);
    cudaGetSymbolAddress((void**)&Vlp,   g_Vl);

    static int attr_set = 0;
    if (!attr_set) {
        cudaFuncSetAttribute(gemm_bf16x3, cudaFuncAttributeMaxDynamicSharedMemorySize, GEMM_SMEM);
        cudaFuncSetAttribute(flash_attn, cudaFuncAttributeMaxDynamicSharedMemorySize, ATT_SMEM);
        attr_set = 1;
    }

    split_rows<<<(S * HID / 4 + 255) / 256, 256>>>(hs, Ahp, Alp, S * HID / 4);
    split_transpose<<<dim3(QKV3 / 32, HID / 32), dim3(32, 8)>>>(Wqkv, Bqh, Bql, KDIM, QKV3);
    split_transpose<<<dim3(HID / 32, HID / 32), dim3(32, 8)>>>(Wd, Bdh, Bdl, KDIM, HID);

    gemm_bf16x3<<<dim3(S / 128, QKV3 / 128), 256, GEMM_SMEM>>>(Ahp, Alp, Bqh, Bql, bqkv, fused, QKV3);

    ln_rope_kernel<<<dim3(S, NH), HD>>>(fused, qw, qb, kw, kb, Qhp, Qlp, Khp, Klp, Vhp, Vlp);

    flash_attn<<<dim3(S / 64, NH), 128, ATT_SMEM>>>(Qhp, Qlp, Khp, Klp, Vhp, Vlp, Ahp, Alp);

    gemm_bf16x3<<<dim3(S / 128, HID / 128), 256, GEMM_SMEM>>>(Ahp, Alp, Bdh, Bdl, bd, out, HID);
}

// round 8
// speedup vs baseline: 4.7702x; 1.2118x over previous
#include <cuda_runtime.h>
#include <cuda_bf16.h>
#include <math.h>
#include <stdint.h>

// Problem constants
#define S    2048
#define HID  4096
#define NH   64
#define HD   64
#define ROT  32
#define QKV3 12288   // 3*HID
#define EPS  1e-5f
#define KDIM 4096
#define BKB  32
#define KITERS (KDIM / BKB)      // 128

// ---------------- scratch (device globals) ----------------
__device__ float g_fused[S * QKV3];
__device__ float g_cos[S * 16];
__device__ float g_sin[S * 16];
__device__ __nv_bfloat16 g_Ah[S * HID];
__device__ __nv_bfloat16 g_Al[S * HID];
__device__ __nv_bfloat16 g_Bqh[QKV3 * HID];
__device__ __nv_bfloat16 g_Bql[QKV3 * HID];
__device__ __nv_bfloat16 g_Bdh[HID * HID];
__device__ __nv_bfloat16 g_Bdl[HID * HID];
__device__ __nv_bfloat16 g_Qh[NH * S * HD];
__device__ __nv_bfloat16 g_Ql[NH * S * HD];
__device__ __nv_bfloat16 g_Kh[NH * S * HD];
__device__ __nv_bfloat16 g_Kl[NH * S * HD];
__device__ __nv_bfloat16 g_Vh[NH * S * HD];
__device__ __nv_bfloat16 g_Vl[NH * S * HD];

// ===================== PTX helpers =====================
__device__ __forceinline__ uint32_t smem_u32(const void* p) {
    uint32_t a;
    asm("{ .reg .u64 t; cvta.to.shared.u64 t, %1; cvt.u32.u64 %0, t; }" : "=r"(a) : "l"(p));
    return a;
}
__device__ __forceinline__ void cp16(uint32_t dst, const void* src) {
    asm volatile("cp.async.cg.shared.global [%0], [%1], 16;\n" :: "r"(dst), "l"(src));
}
__device__ __forceinline__ void cp_commit() { asm volatile("cp.async.commit_group;\n" ::: "memory"); }
__device__ __forceinline__ void cp_wait1()  { asm volatile("cp.async.wait_group 1;\n" ::: "memory"); }

__device__ __forceinline__ void ldsm4(uint32_t* r, uint32_t addr) {
    asm volatile("ldmatrix.sync.aligned.m8n8.x4.shared.b16 {%0,%1,%2,%3}, [%4];"
                 : "=r"(r[0]), "=r"(r[1]), "=r"(r[2]), "=r"(r[3]) : "r"(addr));
}
__device__ __forceinline__ void ldsm4t(uint32_t* r, uint32_t addr) {
    asm volatile("ldmatrix.sync.aligned.m8n8.x4.trans.shared.b16 {%0,%1,%2,%3}, [%4];"
                 : "=r"(r[0]), "=r"(r[1]), "=r"(r[2]), "=r"(r[3]) : "r"(addr));
}
__device__ __forceinline__ void mma16816(float* d, const uint32_t* a, const uint32_t* b) {
    asm volatile("mma.sync.aligned.m16n8k16.row.col.f32.bf16.bf16.f32 "
                 "{%0,%1,%2,%3}, {%4,%5,%6,%7}, {%8,%9}, {%0,%1,%2,%3};"
                 : "+f"(d[0]), "+f"(d[1]), "+f"(d[2]), "+f"(d[3])
                 : "r"(a[0]), "r"(a[1]), "r"(a[2]), "r"(a[3]), "r"(b[0]), "r"(b[1]));
}

__device__ __forceinline__ uint32_t swz64(int row, int kc) {
    return (uint32_t)(row * 64 + ((kc ^ ((row >> 1) & 3)) << 4));
}
__device__ __forceinline__ uint32_t swz128(int row, int c) {
    return (uint32_t)(row * 128 + ((c ^ (row & 7)) << 4));
}

// fast exp2 on fma/alu pipes; rel err ~2.4e-6
__device__ __forceinline__ float fexp2(float x) {
    x = fmaxf(x, -126.0f);
    float t = x + 12582912.0f;
    int   n = __float_as_int(t) - 0x4B400000;
    float f = x - (t - 12582912.0f);
    float p =      1.3333558146e-3f;
    p = fmaf(p, f, 9.6181291076e-3f);
    p = fmaf(p, f, 5.5504108665e-2f);
    p = fmaf(p, f, 2.4022650696e-1f);
    p = fmaf(p, f, 6.9314718056e-1f);
    p = fmaf(p, f, 1.0f);
    return __int_as_float(__float_as_int(p) + (n << 23));
}

// ===================== RoPE cos/sin table (exact reference numerics) =======
__global__ void rope_init(float* __restrict__ cosT, float* __restrict__ sinT)
{
    int idx = blockIdx.x * blockDim.x + threadIdx.x;   // 0 .. 32767
    if (idx >= S * 16) return;
    int s = idx >> 4, f = idx & 15;
    float invf = (float)pow(25000.0, -(double)f / 16.0);
    float ph = (float)s * invf;
    cosT[idx] = cosf(ph);
    sinT[idx] = sinf(ph);
}

// ===================== split / transpose conversion kernels ================
__global__ void split_rows(const float* __restrict__ in, __nv_bfloat16* __restrict__ hi,
                           __nv_bfloat16* __restrict__ lo, int n4)
{
    int i = blockIdx.x * blockDim.x + threadIdx.x;
    if (i >= n4) return;
    float4 v = ((const float4*)in)[i];
    __nv_bfloat16 h0 = __float2bfloat16(v.x);
    __nv_bfloat16 h1 = __float2bfloat16(v.y);
    __nv_bfloat16 h2 = __float2bfloat16(v.z);
    __nv_bfloat16 h3 = __float2bfloat16(v.w);
    __nv_bfloat16 l0 = __float2bfloat16(v.x - __bfloat162float(h0));
    __nv_bfloat16 l1 = __float2bfloat16(v.y - __bfloat162float(h1));
    __nv_bfloat16 l2 = __float2bfloat16(v.z - __bfloat162float(h2));
    __nv_bfloat16 l3 = __float2bfloat16(v.w - __bfloat162float(h3));
    ((__nv_bfloat162*)hi)[2 * i]     = __nv_bfloat162(h0, h1);
    ((__nv_bfloat162*)hi)[2 * i + 1] = __nv_bfloat162(h2, h3);
    ((__nv_bfloat162*)lo)[2 * i]     = __nv_bfloat162(l0, l1);
    ((__nv_bfloat162*)lo)[2 * i + 1] = __nv_bfloat162(l2, l3);
}

__global__ void split_transpose(const float* __restrict__ in, __nv_bfloat16* __restrict__ hi,
                                __nv_bfloat16* __restrict__ lo, int K, int N)
{
    __shared__ float t[32][33];
    const int n0 = blockIdx.x * 32, k0 = blockIdx.y * 32;
    const int tx = threadIdx.x, ty = threadIdx.y;
    #pragma unroll
    for (int r = 0; r < 4; r++)
        t[ty + r * 8][tx] = in[(size_t)(k0 + ty + r * 8) * N + n0 + tx];
    __syncthreads();
    #pragma unroll
    for (int r = 0; r < 4; r++) {
        int n = n0 + ty + r * 8;
        int k = k0 + tx;
        float v = t[tx][ty + r * 8];
        __nv_bfloat16 h = __float2bfloat16(v);
        __nv_bfloat16 l = __float2bfloat16(v - __bfloat162float(h));
        hi[(size_t)n * K + k] = h;
        lo[(size_t)n * K + k] = l;
    }
}

// ===================== bf16x3 tensor-core GEMM =====================
#define STG 32768
#define GEMM_SMEM (3 * STG)

__global__ __launch_bounds__(256, 2)
void gemm_bf16x3(const __nv_bfloat16* __restrict__ Ah, const __nv_bfloat16* __restrict__ Al,
                 const __nv_bfloat16* __restrict__ Bh, const __nv_bfloat16* __restrict__ Bl,
                 const float* __restrict__ bias, float* __restrict__ C, int N)
{
    extern __shared__ __align__(128) char smem[];
    const uint32_t sb = smem_u32(smem);
    const int tid = threadIdx.x, warp = tid >> 5, lane = tid & 31;
    const int wm = warp >> 1, wn = warp & 1;
    const int m0 = blockIdx.x * 128, n0 = blockIdx.y * 128;

    const char* srcs[4] = {
        (const char*)(Ah + (size_t)m0 * KDIM),
        (const char*)(Al + (size_t)m0 * KDIM),
        (const char*)(Bh + (size_t)n0 * KDIM),
        (const char*)(Bl + (size_t)n0 * KDIM)
    };

    const int ldrow0 = tid >> 2, ldc = tid & 3;
    const uint32_t dsw0 = swz64(ldrow0, ldc);
    const uint32_t dsw1 = swz64(ldrow0 + 64, ldc);

    auto load_stage = [&](int st, int kc) {
        uint32_t base = sb + st * STG;
        size_t kb = (size_t)kc * 64;
        #pragma unroll
        for (int mat = 0; mat < 4; mat++) {
            const char* s = srcs[mat];
            uint32_t d = base + mat * 8192;
            cp16(d + dsw0, s + (size_t)ldrow0 * 8192 + kb + ldc * 16);
            cp16(d + dsw1, s + (size_t)(ldrow0 + 64) * 8192 + kb + ldc * 16);
        }
    };

    const int g = lane >> 3, r = lane & 7;
    uint32_t offA[2][2], offB[4][2];
    #pragma unroll
    for (int mt = 0; mt < 2; mt++)
        #pragma unroll
        for (int ks = 0; ks < 2; ks++)
            offA[mt][ks] = swz64(wm * 32 + mt * 16 + (g & 1) * 8 + r, ks * 2 + (g >> 1));
    #pragma unroll
    for (int p = 0; p < 4; p++)
        #pragma unroll
        for (int ks = 0; ks < 2; ks++)
            offB[p][ks] = swz64(wn * 64 + p * 16 + (g >> 1) * 8 + r, ks * 2 + (g & 1));

    float acc[2][8][4];
    #pragma unroll
    for (int mt = 0; mt < 2; mt++)
        #pragma unroll
        for (int nt = 0; nt < 8; nt++)
            #pragma unroll
            for (int q = 0; q < 4; q++) acc[mt][nt][q] = 0.f;

    load_stage(0, 0); cp_commit();
    load_stage(1, 1); cp_commit();

    int st = 0;
    for (int i = 0; i < KITERS; i++) {
        cp_wait1();
        __syncthreads();
        int pst = st + 2; if (pst >= 3) pst -= 3;
        if (i + 2 < KITERS) load_stage(pst, i + 2);
        cp_commit();

        uint32_t base = sb + st * STG;
        #pragma unroll
        for (int ks = 0; ks < 2; ks++) {
            uint32_t ah[2][4], al[2][4], bh[8][2], bl[8][2];
            #pragma unroll
            for (int mt = 0; mt < 2; mt++) {
                ldsm4(ah[mt], base + offA[mt][ks]);
                ldsm4(al[mt], base + 8192 + offA[mt][ks]);
            }
            #pragma unroll
            for (int p = 0; p < 4; p++) {
                uint32_t t4[4];
                ldsm4(t4, base + 16384 + offB[p][ks]);
                bh[2*p][0] = t4[0]; bh[2*p][1] = t4[1];
                bh[2*p+1][0] = t4[2]; bh[2*p+1][1] = t4[3];
                ldsm4(t4, base + 24576 + offB[p][ks]);
                bl[2*p][0] = t4[0]; bl[2*p][1] = t4[1];
                bl[2*p+1][0] = t4[2]; bl[2*p+1][1] = t4[3];
            }
            #pragma unroll
            for (int mt = 0; mt < 2; mt++)
                #pragma unroll
                for (int nt = 0; nt < 8; nt++) {
                    mma16816(acc[mt][nt], ah[mt], bh[nt]);
                    mma16816(acc[mt][nt], ah[mt], bl[nt]);
                    mma16816(acc[mt][nt], al[mt], bh[nt]);
                }
        }
        st += 1; if (st >= 3) st -= 3;
    }

    #pragma unroll
    for (int mt = 0; mt < 2; mt++) {
        int row0 = m0 + wm * 32 + mt * 16 + (lane >> 2);
        #pragma unroll
        for (int nt = 0; nt < 8; nt++) {
            int col = n0 + wn * 64 + nt * 8 + (lane & 3) * 2;
            float bx = __ldg(bias + col), by = __ldg(bias + col + 1);
            float2 v0 = make_float2(acc[mt][nt][0] + bx, acc[mt][nt][1] + by);
            float2 v1 = make_float2(acc[mt][nt][2] + bx, acc[mt][nt][3] + by);
            *(float2*)&C[(size_t)row0 * N + col] = v0;
            *(float2*)&C[(size_t)(row0 + 8) * N + col] = v1;
        }
    }
}

// ---------------- LayerNorm + RoPE (table) -> bf16 hi/lo Q,K,V -------------
__global__ __launch_bounds__(256)
void ln_rope_kernel(const float* __restrict__ fused,
                    const float* __restrict__ qw, const float* __restrict__ qb,
                    const float* __restrict__ kw, const float* __restrict__ kb,
                    const float* __restrict__ cosT, const float* __restrict__ sinT,
                    __nv_bfloat16* __restrict__ Qh, __nv_bfloat16* __restrict__ Ql,
                    __nv_bfloat16* __restrict__ Kh, __nv_bfloat16* __restrict__ Kl,
                    __nv_bfloat16* __restrict__ Vh, __nv_bfloat16* __restrict__ Vl)
{
    const int s = blockIdx.x;
    const int u = threadIdx.x >> 6;
    const int h = blockIdx.y * 4 + u;
    const int d = threadIdx.x & 63;
    const int w2 = (threadIdx.x >> 5) & 1;
    const int lane = threadIdx.x & 31;

    const float* base = fused + (size_t)s * QKV3 + h * (3 * HD);
    float q = base[d];
    float k = base[HD + d];
    float v = base[2 * HD + d];

    __shared__ float sh[4][2];

    auto bsum = [&](float x) -> float {
        #pragma unroll
        for (int o = 16; o; o >>= 1) x += __shfl_xor_sync(0xffffffffu, x, o);
        __syncthreads();
        if (lane == 0) sh[u][w2] = x;
        __syncthreads();
        return sh[u][0] + sh[u][1];
    };

    float mu = bsum(q) * (1.f / HD);
    float dq = q - mu;
    float var = bsum(dq * dq) * (1.f / HD);
    float qn = dq * rsqrtf(var + EPS) * qw[d] + qb[d];

    mu = bsum(k) * (1.f / HD);
    float dk = k - mu;
    var = bsum(dk * dk) * (1.f / HD);
    float kn = dk * rsqrtf(var + EPS) * kw[d] + kb[d];

    float qo = __shfl_xor_sync(0xffffffffu, qn, 16);
    float ko = __shfl_xor_sync(0xffffffffu, kn, 16);
    if (d < ROT) {
        int f = d & 15;
        float c  = cosT[s * 16 + f];
        float si = sinT[s * 16 + f];
        float sign = (d < 16) ? -1.f : 1.f;
        qn = qn * c + sign * qo * si;
        kn = kn * c + sign * ko * si;
    }
    qn *= 0.125f * 1.4426950408889634f;   // 1/sqrt(HD) * log2(e)

    size_t o = ((size_t)h * S + s) * HD + d;
    __nv_bfloat16 qh = __float2bfloat16(qn);
    __nv_bfloat16 kh = __float2bfloat16(kn);
    __nv_bfloat16 vh = __float2bfloat16(v);
    Qh[o] = qh; Ql[o] = __float2bfloat16(qn - __bfloat162float(qh));
    Kh[o] = kh; Kl[o] = __float2bfloat16(kn - __bfloat162float(kh));
    Vh[o] = vh; Vl[o] = __float2bfloat16(v - __bfloat162float(vh));
}

// ---------------- flash attention: 128-q tile, 8 warps, log2 softmax -------
#define ATT_STG0  32768
#define ATT_STGSZ 32768
#define ATT_SMEM  (ATT_STG0 + 2 * ATT_STGSZ)

__global__ __launch_bounds__(256)
void flash_attn(const __nv_bfloat16* __restrict__ Qh, const __nv_bfloat16* __restrict__ Ql,
                const __nv_bfloat16* __restrict__ Kh, const __nv_bfloat16* __restrict__ Kl,
                const __nv_bfloat16* __restrict__ Vh, const __nv_bfloat16* __restrict__ Vl,
                __nv_bfloat16* __restrict__ Oh, __nv_bfloat16* __restrict__ Ol)
{
    extern __shared__ __align__(128) char smem[];
    const uint32_t sb = smem_u32(smem);
    const int h = blockIdx.y;
    const int t = gridDim.x - 1 - blockIdx.x;     // big tiles first
    const int tid = threadIdx.x, warp = tid >> 5, lane = tid & 31;
    const int g = lane >> 3, r = lane & 7;

    const char* qhp = (const char*)(Qh + ((size_t)h * S + t * 128) * HD);
    const char* qlp = (const char*)(Ql + ((size_t)h * S + t * 128) * HD);
    const char* khp = (const char*)(Kh + (size_t)h * S * HD);
    const char* klp = (const char*)(Kl + (size_t)h * S * HD);
    const char* vhp = (const char*)(Vh + (size_t)h * S * HD);
    const char* vlp = (const char*)(Vl + (size_t)h * S * HD);

    // preload Q (128 rows, hi+lo)
    for (int i = tid; i < 1024; i += 256) {
        int row = i >> 3, c = i & 7;
        uint32_t o = swz128(row, c);
        cp16(sb + o, qhp + row * 128 + c * 16);
        cp16(sb + 16384 + o, qlp + row * 128 + c * 16);
    }
    auto load_kv = [&](int st, int kt) {
        uint32_t base = sb + ATT_STG0 + st * ATT_STGSZ;
        size_t gro = (size_t)kt * 64 * 128;
        for (int i = tid; i < 512; i += 256) {
            int row = i >> 3, c = i & 7;
            uint32_t o = swz128(row, c);
            size_t go = gro + row * 128 + c * 16;
            cp16(base + o,          khp + go);
            cp16(base + 8192 + o,   klp + go);
            cp16(base + 16384 + o,  vhp + go);
            cp16(base + 24576 + o,  vlp + go);
        }
    };
    load_kv(0, 0);
    cp_commit();

    uint32_t aQh[4][4], aQl[4][4];
    uint32_t offA[4];
    #pragma unroll
    for (int kc = 0; kc < 4; kc++)
        offA[kc] = swz128(warp * 16 + (g & 1) * 8 + r, kc * 2 + (g >> 1));

    float accO[8][4];
    #pragma unroll
    for (int nt = 0; nt < 8; nt++)
        #pragma unroll
        for (int c = 0; c < 4; c++) accO[nt][c] = 0.f;
    float m0 = -1e30f, m1 = -1e30f, l0 = 0.f, l1 = 0.f;

    const int qg0   = t * 128 + warp * 16 + (lane >> 2);  // this thread's first q row
    const int qbase = t * 128 + warp * 16;                // warp's first q row
    const int qmax  = qbase + 15;                         // warp's last q row
    const int kmax  = 2 * t + 1;

    int st = 0;
    for (int kt = 0; kt <= kmax; kt++) {
        __syncthreads();
        if (kt + 1 <= kmax) load_kv(st ^ 1, kt + 1);
        cp_commit();
        cp_wait1();
        __syncthreads();

        if (kt == 0) {
            #pragma unroll
            for (int kc = 0; kc < 4; kc++) {
                ldsm4(aQh[kc], sb + offA[kc]);
                ldsm4(aQl[kc], sb + 16384 + offA[kc]);
            }
        }

        if (kt * 64 > qmax) { st ^= 1; continue; }   // warp fully masked

        uint32_t base = sb + ATT_STG0 + st * ATT_STGSZ;

        float s[8][4];
        #pragma unroll
        for (int nt = 0; nt < 8; nt++)
            #pragma unroll
            for (int c = 0; c < 4; c++) s[nt][c] = 0.f;
        #pragma unroll
        for (int kc = 0; kc < 4; kc++) {
            #pragma unroll
            for (int p = 0; p < 4; p++) {
                uint32_t offb = swz128(p * 16 + (g >> 1) * 8 + r, kc * 2 + (g & 1));
                uint32_t th[4], tl[4];
                ldsm4(th, base + offb);
                ldsm4(tl, base + 8192 + offb);
                mma16816(s[2*p],   aQh[kc], th);
                mma16816(s[2*p+1], aQh[kc], th + 2);
                mma16816(s[2*p],   aQh[kc], tl);
                mma16816(s[2*p+1], aQh[kc], tl + 2);
                mma16816(s[2*p],   aQl[kc], th);
                mma16816(s[2*p+1], aQl[kc], th + 2);
            }
        }

        // causal mask: apply whenever the tile's last key exceeds the warp's FIRST row
        if (kt * 64 + 63 > qbase) {
            #pragma unroll
            for (int nt = 0; nt < 8; nt++) {
                int kg = kt * 64 + nt * 8 + (lane & 3) * 2;
                if (kg > qg0)         s[nt][0] = -1e30f;
                if (kg + 1 > qg0)     s[nt][1] = -1e30f;
                if (kg > qg0 + 8)     s[nt][2] = -1e30f;
                if (kg + 1 > qg0 + 8) s[nt][3] = -1e30f;
            }
        }

        float mx0 = -1e30f, mx1 = -1e30f;
        #pragma unroll
        for (int nt = 0; nt < 8; nt++) {
            mx0 = fmaxf(mx0, fmaxf(s[nt][0], s[nt][1]));
            mx1 = fmaxf(mx1, fmaxf(s[nt][2], s[nt][3]));
        }
        mx0 = fmaxf(mx0, __shfl_xor_sync(0xffffffffu, mx0, 1));
        mx0 = fmaxf(mx0, __shfl_xor_sync(0xffffffffu, mx0, 2));
        mx1 = fmaxf(mx1, __shfl_xor_sync(0xffffffffu, mx1, 1));
        mx1 = fmaxf(mx1, __shfl_xor_sync(0xffffffffu, mx1, 2));
        float mn0 = fmaxf(m0, mx0), mn1 = fmaxf(m1, mx1);
        float corr0 = fexp2(m0 - mn0), corr1 = fexp2(m1 - mn1);
        m0 = mn0; m1 = mn1;
        l0 *= corr0; l1 *= corr1;
        #pragma unroll
        for (int nt = 0; nt < 8; nt++) {
            accO[nt][0] *= corr0; accO[nt][1] *= corr0;
            accO[nt][2] *= corr1; accO[nt][3] *= corr1;
        }

        uint32_t Ph0[8], Ph1[8], Pl0[8], Pl1[8];
        #pragma unroll
        for (int nt = 0; nt < 8; nt++) {
            float p0 = fexp2(s[nt][0] - m0);
            float p1 = fexp2(s[nt][1] - m0);
            float p2 = fexp2(s[nt][2] - m1);
            float p3 = fexp2(s[nt][3] - m1);
            l0 += p0 + p1; l1 += p2 + p3;
            __nv_bfloat162 h01 = __floats2bfloat162_rn(p0, p1);
            __nv_bfloat162 h23 = __floats2bfloat162_rn(p2, p3);
            __nv_bfloat162 q01 = __floats2bfloat162_rn(p0 - __low2float(h01), p1 - __high2float(h01));
            __nv_bfloat162 q23 = __floats2bfloat162_rn(p2 - __low2float(h23), p3 - __high2float(h23));
            Ph0[nt] = *(uint32_t*)&h01; Ph1[nt] = *(uint32_t*)&h23;
            Pl0[nt] = *(uint32_t*)&q01; Pl1[nt] = *(uint32_t*)&q23;
        }

        #pragma unroll
        for (int kc = 0; kc < 4; kc++) {
            uint32_t aPh[4] = {Ph0[2*kc], Ph1[2*kc], Ph0[2*kc+1], Ph1[2*kc+1]};
            uint32_t aPl[4] = {Pl0[2*kc], Pl1[2*kc], Pl0[2*kc+1], Pl1[2*kc+1]};
            #pragma unroll
            for (int p = 0; p < 4; p++) {
                uint32_t offv = swz128(kc * 16 + (g & 1) * 8 + r, p * 2 + (g >> 1));
                uint32_t vh[4], vl[4];
                ldsm4t(vh, base + 16384 + offv);
                ldsm4t(vl, base + 24576 + offv);
                mma16816(accO[2*p],   aPh, vh);
                mma16816(accO[2*p+1], aPh, vh + 2);
                mma16816(accO[2*p],   aPh, vl);
                mma16816(accO[2*p+1], aPh, vl + 2);
                mma16816(accO[2*p],   aPl, vh);
                mma16816(accO[2*p+1], aPl, vh + 2);
            }
        }
        st ^= 1;
    }

    l0 += __shfl_xor_sync(0xffffffffu, l0, 1);
    l0 += __shfl_xor_sync(0xffffffffu, l0, 2);
    l1 += __shfl_xor_sync(0xffffffffu, l1, 1);
    l1 += __shfl_xor_sync(0xffffffffu, l1, 2);
    float inv0 = 1.f / l0, inv1 = 1.f / l1;
    int r0 = t * 128 + warp * 16 + (lane >> 2);
    #pragma unroll
    for (int nt = 0; nt < 8; nt++) {
        int col = h * 64 + nt * 8 + (lane & 3) * 2;
        float o0 = accO[nt][0] * inv0, o1 = accO[nt][1] * inv0;
        float o2 = accO[nt][2] * inv1, o3 = accO[nt][3] * inv1;
        __nv_bfloat162 h01 = __floats2bfloat162_rn(o0, o1);
        __nv_bfloat162 h23 = __floats2bfloat162_rn(o2, o3);
        __nv_bfloat162 q01 = __floats2bfloat162_rn(o0 - __low2float(h01), o1 - __high2float(h01));
        __nv_bfloat162 q23 = __floats2bfloat162_rn(o2 - __low2float(h23), o3 - __high2float(h23));
        *(__nv_bfloat162*)&Oh[(size_t)r0 * HID + col] = h01;
        *(__nv_bfloat162*)&Ol[(size_t)r0 * HID + col] = q01;
        *(__nv_bfloat162*)&Oh[(size_t)(r0 + 8) * HID + col] = h23;
        *(__nv_bfloat162*)&Ol[(size_t)(r0 + 8) * HID + col] = q23;
    }
}

// ---------------- launch ---------------------------------------------------
extern "C" void kernel_launch(void* const* d_in, const int* in_sizes, int n_in,
                              void* d_out, int out_size)
{
    const float* hs    = (const float*)d_in[0];
    const float* Wqkv  = (const float*)d_in[3];
    const float* bqkv  = (const float*)d_in[4];
    const float* Wd    = (const float*)d_in[5];
    const float* bd    = (const float*)d_in[6];
    const float* qw    = (const float*)d_in[7];
    const float* qb    = (const float*)d_in[8];
    const float* kw    = (const float*)d_in[9];
    const float* kb    = (const float*)d_in[10];
    float* out = (float*)d_out;

    float *fused, *cosT, *sinT;
    __nv_bfloat16 *Ahp, *Alp, *Bqh, *Bql, *Bdh, *Bdl;
    __nv_bfloat16 *Qhp, *Qlp, *Khp, *Klp, *Vhp, *Vlp;
    cudaGetSymbolAddress((void**)&fused, g_fused);
    cudaGetSymbolAddress((void**)&cosT,  g_cos);
    cudaGetSymbolAddress((void**)&sinT,  g_sin);
    cudaGetSymbolAddress((void**)&Ahp,   g_Ah);
    cudaGetSymbolAddress((void**)&Alp,   g_Al);
    cudaGetSymbolAddress((void**)&Bqh,   g_Bqh);
    cudaGetSymbolAddress((void**)&Bql,   g_Bql);
    cudaGetSymbolAddress((void**)&Bdh,   g_Bdh);
    cudaGetSymbolAddress((void**)&Bdl,   g_Bdl);
    cudaGetSymbolAddress((void**)&Qhp,   g_Qh);
    cudaGetSymbolAddress((void**)&Qlp,   g_Ql);
    cudaGetSymbolAddress((void**)&Khp,   g_Kh);
    cudaGetSymbolAddress((void**)&Klp,   g_Kl);
    cudaGetSymbolAddress((void**)&Vhp,   g_Vh);
    cudaGetSymbolAddress((void**)&Vlp,   g_Vl);

    static int attr_set = 0;
    if (!attr_set) {
        cudaFuncSetAttribute(gemm_bf16x3, cudaFuncAttributeMaxDynamicSharedMemorySize, GEMM_SMEM);
        cudaFuncSetAttribute(flash_attn, cudaFuncAttributeMaxDynamicSharedMemorySize, ATT_SMEM);
        attr_set = 1;
    }

    rope_init<<<(S * 16 + 255) / 256, 256>>>(cosT, sinT);
    split_rows<<<(S * HID / 4 + 255) / 256, 256>>>(hs, Ahp, Alp, S * HID / 4);
    split_transpose<<<dim3(QKV3 / 32, HID / 32), dim3(32, 8)>>>(Wqkv, Bqh, Bql, KDIM, QKV3);
    split_transpose<<<dim3(HID / 32, HID / 32), dim3(32, 8)>>>(Wd, Bdh, Bdl, KDIM, HID);

    gemm_bf16x3<<<dim3(S / 128, QKV3 / 128), 256, GEMM_SMEM>>>(Ahp, Alp, Bqh, Bql, bqkv, fused, QKV3);

    ln_rope_kernel<<<dim3(S, NH / 4), 256>>>(fused, qw, qb, kw, kb, cosT, sinT,
                                             Qhp, Qlp, Khp, Klp, Vhp, Vlp);

    flash_attn<<<dim3(S / 128, NH), 256, ATT_SMEM>>>(Qhp, Qlp, Khp, Klp, Vhp, Vlp, Ahp, Alp);

    gemm_bf16x3<<<dim3(S / 128, HID / 128), 256, GEMM_SMEM>>>(Ahp, Alp, Bdh, Bdl, bd, out, HID);
}